// round 1
// baseline (speedup 1.0000x reference)
#include <cuda_runtime.h>
#include <math.h>

#define NTOK 4096
#define HID  1024
#define SQ   2048
#define NH   16
#define HD   64
#define PRIME_SCALE_F 0.047245559126404574f  /* 1/sqrt(7*64) */

// Scratch (allocation-free rule: device globals)
__device__ float g_q[NTOK * HID];
__device__ float g_k[NTOK * HID];
__device__ float g_v[NTOK * HID];
__device__ float g_base[NTOK * HID];
__device__ float g_ent;

__global__ void init_kernel() { g_ent = 0.0f; }

// ---------------------------------------------------------------------------
// 128x128x8 fp32 SIMT GEMM: C[m,n] = sum_k A[m,k] * W[n,k]   (both K-major)
// 256 threads, 8x8 micro-tile per thread.
// ---------------------------------------------------------------------------
__device__ __forceinline__ void gemm_core(const float* __restrict__ A,
                                          const float* __restrict__ W,
                                          int m0, int n0,
                                          float (&acc)[8][8],
                                          float (&As)[8][128],
                                          float (&Bs)[8][128]) {
    const int t  = threadIdx.x;
    const int lr = t >> 1;          // 0..127
    const int lk = (t & 1) * 4;     // 0 or 4
    const int ty = t >> 4, tx = t & 15;

    for (int k0 = 0; k0 < HID; k0 += 8) {
        __syncthreads();
        float4 av = *(const float4*)&A[(size_t)(m0 + lr) * HID + k0 + lk];
        float4 bv = *(const float4*)&W[(size_t)(n0 + lr) * HID + k0 + lk];
        As[lk + 0][lr] = av.x; As[lk + 1][lr] = av.y;
        As[lk + 2][lr] = av.z; As[lk + 3][lr] = av.w;
        Bs[lk + 0][lr] = bv.x; Bs[lk + 1][lr] = bv.y;
        Bs[lk + 2][lr] = bv.z; Bs[lk + 3][lr] = bv.w;
        __syncthreads();
#pragma unroll
        for (int kk = 0; kk < 8; kk++) {
            float a[8], b[8];
            *(float4*)&a[0] = *(const float4*)&As[kk][ty * 8];
            *(float4*)&a[4] = *(const float4*)&As[kk][ty * 8 + 4];
            *(float4*)&b[0] = *(const float4*)&Bs[kk][tx * 8];
            *(float4*)&b[4] = *(const float4*)&Bs[kk][tx * 8 + 4];
#pragma unroll
            for (int i = 0; i < 8; i++)
#pragma unroll
                for (int j = 0; j < 8; j++)
                    acc[i][j] = fmaf(a[i], b[j], acc[i][j]);
        }
    }
}

// QKV projection. grid (32, 8, 3). Writes head-major [B,H,S,D].
__global__ void __launch_bounds__(256) qkv_gemm(const float* __restrict__ x,
                                                const float* __restrict__ qw, const float* __restrict__ qb,
                                                const float* __restrict__ kw, const float* __restrict__ kb,
                                                const float* __restrict__ vw, const float* __restrict__ vb) {
    __shared__ float As[8][128];
    __shared__ float Bs[8][128];
    const int m0 = blockIdx.x * 128, n0 = blockIdx.y * 128;
    const int which = blockIdx.z;
    const float* W; const float* bias; float* dst; float scl;
    if (which == 0)      { W = qw; bias = qb; dst = g_q; scl = PRIME_SCALE_F; }
    else if (which == 1) { W = kw; bias = kb; dst = g_k; scl = 1.0f; }
    else                 { W = vw; bias = vb; dst = g_v; scl = 1.0f; }

    float acc[8][8] = {};
    gemm_core(x, W, m0, n0, acc, As, Bs);

    const int ty = threadIdx.x >> 4, tx = threadIdx.x & 15;
#pragma unroll
    for (int i = 0; i < 8; i++) {
        int m = m0 + ty * 8 + i;
        int bb = m >> 11, s = m & 2047;
#pragma unroll
        for (int j = 0; j < 8; j++) {
            int o = n0 + tx * 8 + j;
            int h = o >> 6, d = o & 63;
            float v = (acc[i][j] + bias[o]) * scl;
            dst[(((size_t)(bb * NH + h)) * SQ + s) * HD + d] = v;
        }
    }
}

// Output projection with entropy-gated scale. grid (32, 8).
__global__ void __launch_bounds__(256) out_gemm(const float* __restrict__ ow,
                                                const float* __restrict__ ob,
                                                float* __restrict__ out,
                                                float c_full) {
    __shared__ float As[8][128];
    __shared__ float Bs[8][128];
    const int m0 = blockIdx.x * 128, n0 = blockIdx.y * 128;

    float acc[8][8] = {};
    gemm_core(g_base, ow, m0, n0, acc, As, Bs);

    float avg_ent = g_ent * (1.0f / (float)(NTOK * NH));
    float scale = (avg_ent < 0.2f) ? 1.0f : c_full;

    const int ty = threadIdx.x >> 4, tx = threadIdx.x & 15;
#pragma unroll
    for (int i = 0; i < 8; i++) {
        int m = m0 + ty * 8 + i;
#pragma unroll
        for (int j = 0; j < 8; j++) {
            int o = n0 + tx * 8 + j;
            out[(size_t)m * HID + o] = fmaf(scale, acc[i][j], ob[o]);
        }
    }
}

// ---------------------------------------------------------------------------
// Flash attention. grid (S/64 = 32 q-tiles, B*H = 32). 256 threads.
// Q/K tiles stored d-major [64][64] in smem, V natural [64][64], S r-major.
// Online softmax + entropy accumulator (H = m + log L - (sum p*s)/L).
// ---------------------------------------------------------------------------
#define ATTN_SMEM ((4096 + 4096 + 4096 + 5 * 64) * 4)

__global__ void __launch_bounds__(256) attn_kernel(const int* __restrict__ amask) {
    extern __shared__ float sm[];
    float* Qs   = sm;                  // [d][r]
    float* KVs  = sm + 4096;           // K: [d][c]; V: [c][n]
    float* Ss   = sm + 8192;           // [r][c]
    float* mrow = sm + 12288;          // 64
    float* lrow = mrow + 64;
    float* trow = lrow + 64;
    float* crow = trow + 64;
    float* kmsk = crow + 64;

    const int t  = threadIdx.x;
    const int bh = blockIdx.y;
    const int q0 = blockIdx.x * 64;
    const int bb = bh >> 4;
    const int hh = bh & 15;

    const float* qp  = g_q + ((size_t)bh * SQ + q0) * HD;
    const float* kpB = g_k + (size_t)bh * SQ * HD;
    const float* vpB = g_v + (size_t)bh * SQ * HD;

    // Load Q tile transposed to [d][r]
#pragma unroll
    for (int i = 0; i < 4; i++) {
        int idx = t + i * 256;
        int r = idx >> 4;
        int dq = (idx & 15) * 4;
        float4 v = *(const float4*)&qp[r * HD + dq];
        Qs[(dq + 0) * 64 + r] = v.x; Qs[(dq + 1) * 64 + r] = v.y;
        Qs[(dq + 2) * 64 + r] = v.z; Qs[(dq + 3) * 64 + r] = v.w;
    }
    if (t < 64) { mrow[t] = -1e30f; lrow[t] = 0.0f; trow[t] = 0.0f; }

    const int ty = t >> 4, tx = t & 15;
    const int r0 = ty * 4, c0 = tx * 4;
    float oacc[4][4] = {};

    for (int kt = 0; kt < 32; kt++) {
        __syncthreads();  // protect KVs/Ss reuse from previous iter
        // Load K tile transposed to [d][c]
        const float* kp = kpB + kt * 64 * HD;
#pragma unroll
        for (int i = 0; i < 4; i++) {
            int idx = t + i * 256;
            int r = idx >> 4;
            int dq = (idx & 15) * 4;
            float4 v = *(const float4*)&kp[r * HD + dq];
            KVs[(dq + 0) * 64 + r] = v.x; KVs[(dq + 1) * 64 + r] = v.y;
            KVs[(dq + 2) * 64 + r] = v.z; KVs[(dq + 3) * 64 + r] = v.w;
        }
        if (t < 64)
            kmsk[t] = amask[bb * SQ + kt * 64 + t] ? 0.0f : -1e30f;
        __syncthreads();

        // S = Q K^T  (64x64, k-depth 64)
        float sacc[4][4] = {};
#pragma unroll 8
        for (int d = 0; d < 64; d++) {
            float4 a4 = *(const float4*)&Qs[d * 64 + r0];
            float4 b4 = *(const float4*)&KVs[d * 64 + c0];
            float av[4] = {a4.x, a4.y, a4.z, a4.w};
            float bv[4] = {b4.x, b4.y, b4.z, b4.w};
#pragma unroll
            for (int i = 0; i < 4; i++)
#pragma unroll
                for (int j = 0; j < 4; j++)
                    sacc[i][j] = fmaf(av[i], bv[j], sacc[i][j]);
        }
#pragma unroll
        for (int i = 0; i < 4; i++) {
            float4 sv;
            sv.x = sacc[i][0] + kmsk[c0 + 0];
            sv.y = sacc[i][1] + kmsk[c0 + 1];
            sv.z = sacc[i][2] + kmsk[c0 + 2];
            sv.w = sacc[i][3] + kmsk[c0 + 3];
            *(float4*)&Ss[(r0 + i) * 64 + c0] = sv;
        }
        __syncthreads();

        // Online softmax: warp w handles rows w*8 .. w*8+7
        {
            const int w = t >> 5, lane = t & 31;
#pragma unroll
            for (int rr = 0; rr < 8; rr++) {
                int r = w * 8 + rr;
                float s1 = Ss[r * 64 + lane];
                float s2 = Ss[r * 64 + lane + 32];
                float mx = fmaxf(s1, s2);
#pragma unroll
                for (int o = 16; o; o >>= 1)
                    mx = fmaxf(mx, __shfl_xor_sync(0xffffffffu, mx, o));
                float mold = mrow[r];
                float mnew = fmaxf(mold, mx);
                float p1 = __expf(s1 - mnew);
                float p2 = __expf(s2 - mnew);
                float ls = p1 + p2;
                float ts = fmaf(p1, s1, p2 * s2);
#pragma unroll
                for (int o = 16; o; o >>= 1) {
                    ls += __shfl_xor_sync(0xffffffffu, ls, o);
                    ts += __shfl_xor_sync(0xffffffffu, ts, o);
                }
                Ss[r * 64 + lane]      = p1;
                Ss[r * 64 + lane + 32] = p2;
                __syncwarp();
                if (lane == 0) {
                    float cf = __expf(mold - mnew);
                    mrow[r] = mnew;
                    lrow[r] = fmaf(lrow[r], cf, ls);
                    trow[r] = fmaf(trow[r], cf, ts);
                    crow[r] = cf;
                }
                __syncwarp();
            }
        }
        __syncthreads();

        // Rescale O accumulators; load V tile (natural [c][n]) over K tile
#pragma unroll
        for (int i = 0; i < 4; i++) {
            float cf = crow[r0 + i];
#pragma unroll
            for (int j = 0; j < 4; j++) oacc[i][j] *= cf;
        }
        const float* vp = vpB + kt * 64 * HD;
#pragma unroll
        for (int i = 0; i < 4; i++) {
            int idx = t + i * 256;
            int c = idx >> 4;
            int nq = (idx & 15) * 4;
            *(float4*)&KVs[c * 64 + nq] = *(const float4*)&vp[c * HD + nq];
        }
        __syncthreads();

        // O += P V
#pragma unroll 4
        for (int c4 = 0; c4 < 16; c4++) {
            float4 pa[4], vb[4];
#pragma unroll
            for (int i = 0; i < 4; i++)
                pa[i] = *(const float4*)&Ss[(r0 + i) * 64 + c4 * 4];
#pragma unroll
            for (int k = 0; k < 4; k++)
                vb[k] = *(const float4*)&KVs[(c4 * 4 + k) * 64 + c0];
#pragma unroll
            for (int i = 0; i < 4; i++) {
                float pv[4] = {pa[i].x, pa[i].y, pa[i].z, pa[i].w};
#pragma unroll
                for (int k = 0; k < 4; k++) {
                    float vv[4] = {vb[k].x, vb[k].y, vb[k].z, vb[k].w};
#pragma unroll
                    for (int j = 0; j < 4; j++)
                        oacc[i][j] = fmaf(pv[k], vv[j], oacc[i][j]);
                }
            }
        }
    }

    // Write normalized O to merged [B,S,HIDDEN] layout
#pragma unroll
    for (int i = 0; i < 4; i++) {
        int r = r0 + i;
        float inv = 1.0f / lrow[r];
        float4 ov;
        ov.x = oacc[i][0] * inv; ov.y = oacc[i][1] * inv;
        ov.z = oacc[i][2] * inv; ov.w = oacc[i][3] * inv;
        *(float4*)&g_base[((size_t)(bb * SQ + q0 + r)) * HID + hh * HD + c0] = ov;
    }

    // Entropy: H_row = m + log(L) - t/L ; block-sum then one atomic
    __syncthreads();
    if (t < 64) {
        float l = lrow[t];
        Ss[t] = mrow[t] + __logf(l) - trow[t] / l;
    }
    __syncthreads();
    if (t == 0) {
        float s = 0.0f;
#pragma unroll 8
        for (int r = 0; r < 64; r++) s += Ss[r];
        atomicAdd(&g_ent, s);
    }
}

extern "C" void kernel_launch(void* const* d_in, const int* in_sizes, int n_in,
                              void* d_out, int out_size) {
    const float* x  = (const float*)d_in[0];
    const float* qw = (const float*)d_in[1];
    const float* qb = (const float*)d_in[2];
    const float* kw = (const float*)d_in[3];
    const float* kb = (const float*)d_in[4];
    const float* vw = (const float*)d_in[5];
    const float* vb = (const float*)d_in[6];
    const float* ow = (const float*)d_in[7];
    const float* ob = (const float*)d_in[8];
    const int* amask = (const int*)d_in[9];
    float* out = (float*)d_out;

    // Collapse the deterministic blend loop: full = c * base
    double c = 1.0;
    for (int i = 1; i < 10; i++) {
        double blend = 1.0 / (1.0 + exp(-(double)i / 10.0));
        double rs = 0.5 + 0.5 * blend;
        c = (1.0 - blend) * c + blend * rs;
    }

    cudaFuncSetAttribute(attn_kernel, cudaFuncAttributeMaxDynamicSharedMemorySize,
                         ATTN_SMEM);

    init_kernel<<<1, 1>>>();
    qkv_gemm<<<dim3(32, 8, 3), 256>>>(x, qw, qb, kw, kb, vw, vb);
    attn_kernel<<<dim3(32, 32), 256, ATTN_SMEM>>>(amask);
    out_gemm<<<dim3(32, 8), 256>>>(ow, ob, out, (float)c);
}

// round 7
// speedup vs baseline: 3.0406x; 3.0406x over previous
#include <cuda_runtime.h>
#include <math.h>
#include <stdint.h>

#define NTOK 4096
#define HID  1024
#define SQ   2048
#define NH   16
#define HD   64
#define PRIME_SCALE_F 0.047245559126404574f  /* 1/sqrt(7*64) */

// Scratch (allocation-free rule: device globals)
__device__ float g_q[NTOK * HID];     // tf32-rounded values, [B,H,S,D]
__device__ float g_k[NTOK * HID];
__device__ float g_v[NTOK * HID];
__device__ float g_base[NTOK * HID];  // fp32, [B,S,HID]
__device__ float g_ent;

__global__ void init_kernel() { g_ent = 0.0f; }

// ---------------------------------------------------------------------------
// helpers
// ---------------------------------------------------------------------------
__device__ __forceinline__ uint32_t f2tf(float f) {
    uint32_t r;
    asm("cvt.rna.tf32.f32 %0, %1;" : "=r"(r) : "f"(f));
    return r;
}

__device__ __forceinline__ void mma8(float* c,
                                     uint32_t a0, uint32_t a1, uint32_t a2, uint32_t a3,
                                     uint32_t b0, uint32_t b1) {
    asm volatile(
        "mma.sync.aligned.m16n8k8.row.col.f32.tf32.tf32.f32 "
        "{%0,%1,%2,%3},{%4,%5,%6,%7},{%8,%9},{%0,%1,%2,%3};"
        : "+f"(c[0]), "+f"(c[1]), "+f"(c[2]), "+f"(c[3])
        : "r"(a0), "r"(a1), "r"(a2), "r"(a3), "r"(b0), "r"(b1));
}

// exp(x) on the FMA pipe (no MUFU). ~1e-7 rel err. Safe for x in [-inf, ~0].
__device__ __forceinline__ float fexp(float x) {
    x = fmaxf(x, -80.0f);
    float y = x * 1.4426950408889634f;
    float z = y + 12582912.0f;                 // round-to-nearest-int trick
    int   n = __float_as_int(z) << 23;         // == n_int << 23 exactly
    float f = y - (z - 12582912.0f);           // frac in [-0.5, 0.5]
    float p = 1.5403531e-4f;
    p = fmaf(p, f, 1.3333558e-3f);
    p = fmaf(p, f, 9.6181291e-3f);
    p = fmaf(p, f, 5.5504109e-2f);
    p = fmaf(p, f, 2.4022651e-1f);
    p = fmaf(p, f, 6.9314718e-1f);
    p = fmaf(p, f, 1.0f);
    return __int_as_float(__float_as_int(p) + n);
}

// ---------------------------------------------------------------------------
// TF32 GEMM core: C[128x128] = A[m0.., K=1024] * B[n0.., K=1024]^T
// Both inputs K-major row-major. 8 warps (2x4), warp tile 64x32.
// Smem: As/Bs double buffered [2][128][36] floats each (tf32-rounded bits).
// ---------------------------------------------------------------------------
#define GP 36
#define GSTRIDE (128 * GP)

__device__ __forceinline__ void gemm_core_tf32(
    const float* __restrict__ A, const float* __restrict__ B,
    int m0, int n0, float* As, float* Bs, float acc[4][4][4]) {
    const int t = threadIdx.x;
    const int w = t >> 5, lane = t & 31;
    const int wm = w >> 2, wn = w & 3;
    const int g = lane >> 2, tig = lane & 3;
    const int lr = t >> 3;           // 0..31
    const int lc = (t & 7) << 2;     // 0..28

    const float* ga = A + (size_t)(m0 + lr) * HID + lc;
    const float* gb = B + (size_t)(n0 + lr) * HID + lc;

    // prologue: stage 0
#pragma unroll
    for (int p = 0; p < 4; p++) {
        float4 av = *(const float4*)(ga + (size_t)p * 32 * HID);
        float4 bv = *(const float4*)(gb + (size_t)p * 32 * HID);
        float4 ac, bc;
        ac.x = __uint_as_float(f2tf(av.x)); ac.y = __uint_as_float(f2tf(av.y));
        ac.z = __uint_as_float(f2tf(av.z)); ac.w = __uint_as_float(f2tf(av.w));
        bc.x = __uint_as_float(f2tf(bv.x)); bc.y = __uint_as_float(f2tf(bv.y));
        bc.z = __uint_as_float(f2tf(bv.z)); bc.w = __uint_as_float(f2tf(bv.w));
        *(float4*)(As + (lr + p * 32) * GP + lc) = ac;
        *(float4*)(Bs + (lr + p * 32) * GP + lc) = bc;
    }
    __syncthreads();

    for (int s = 0; s < 32; s++) {
        float4 pa[4], pb[4];
        if (s < 31) {
#pragma unroll
            for (int p = 0; p < 4; p++) {
                pa[p] = *(const float4*)(ga + (s + 1) * 32 + (size_t)p * 32 * HID);
                pb[p] = *(const float4*)(gb + (s + 1) * 32 + (size_t)p * 32 * HID);
            }
        }
        const float* Ac = As + (s & 1) * GSTRIDE;
        const float* Bc = Bs + (s & 1) * GSTRIDE;
#pragma unroll
        for (int kf = 0; kf < 4; kf++) {
            uint32_t af[4][4], bf[4][2];
#pragma unroll
            for (int mf = 0; mf < 4; mf++) {
                const float* p0 = Ac + (wm * 64 + mf * 16 + g) * GP + kf * 8 + tig;
                af[mf][0] = __float_as_uint(p0[0]);
                af[mf][1] = __float_as_uint(p0[8 * GP]);
                af[mf][2] = __float_as_uint(p0[4]);
                af[mf][3] = __float_as_uint(p0[8 * GP + 4]);
            }
#pragma unroll
            for (int nf = 0; nf < 4; nf++) {
                const float* p0 = Bc + (wn * 32 + nf * 8 + g) * GP + kf * 8 + tig;
                bf[nf][0] = __float_as_uint(p0[0]);
                bf[nf][1] = __float_as_uint(p0[4]);
            }
#pragma unroll
            for (int mf = 0; mf < 4; mf++)
#pragma unroll
                for (int nf = 0; nf < 4; nf++)
                    mma8(acc[mf][nf], af[mf][0], af[mf][1], af[mf][2], af[mf][3],
                         bf[nf][0], bf[nf][1]);
        }
        if (s < 31) {
            float* da = As + ((s + 1) & 1) * GSTRIDE;
            float* db = Bs + ((s + 1) & 1) * GSTRIDE;
#pragma unroll
            for (int p = 0; p < 4; p++) {
                float4 ac, bc;
                ac.x = __uint_as_float(f2tf(pa[p].x)); ac.y = __uint_as_float(f2tf(pa[p].y));
                ac.z = __uint_as_float(f2tf(pa[p].z)); ac.w = __uint_as_float(f2tf(pa[p].w));
                bc.x = __uint_as_float(f2tf(pb[p].x)); bc.y = __uint_as_float(f2tf(pb[p].y));
                bc.z = __uint_as_float(f2tf(pb[p].z)); bc.w = __uint_as_float(f2tf(pb[p].w));
                *(float4*)(da + (lr + p * 32) * GP + lc) = ac;
                *(float4*)(db + (lr + p * 32) * GP + lc) = bc;
            }
        }
        __syncthreads();
    }
}

// QKV projection. grid (32, 8, 3). Writes tf32-rounded head-major [B,H,S,D].
__global__ void __launch_bounds__(256) qkv_gemm(const float* __restrict__ x,
    const float* __restrict__ qw, const float* __restrict__ qb,
    const float* __restrict__ kw, const float* __restrict__ kb,
    const float* __restrict__ vw, const float* __restrict__ vb) {
    extern __shared__ float smf[];
    float* As = smf;
    float* Bs = smf + 2 * GSTRIDE;
    const int m0 = blockIdx.x * 128, n0 = blockIdx.y * 128;
    const float* W; const float* bias; float* dst; float scl;
    if (blockIdx.z == 0)      { W = qw; bias = qb; dst = g_q; scl = PRIME_SCALE_F; }
    else if (blockIdx.z == 1) { W = kw; bias = kb; dst = g_k; scl = 1.0f; }
    else                      { W = vw; bias = vb; dst = g_v; scl = 1.0f; }

    float acc[4][4][4] = {};
    gemm_core_tf32(x, W, m0, n0, As, Bs, acc);

    const int t = threadIdx.x, w = t >> 5, lane = t & 31;
    const int g = lane >> 2, tig = lane & 3;
    const int wm = w >> 2, wn = w & 3;
#pragma unroll
    for (int mf = 0; mf < 4; mf++) {
#pragma unroll
        for (int e = 0; e < 2; e++) {
            int m = m0 + wm * 64 + mf * 16 + g + e * 8;
            int bb = m >> 11, ss = m & 2047;
#pragma unroll
            for (int nf = 0; nf < 4; nf++) {
#pragma unroll
                for (int j = 0; j < 2; j++) {
                    int n = n0 + wn * 32 + nf * 8 + 2 * tig + j;
                    float v = (acc[mf][nf][e * 2 + j] + bias[n]) * scl;
                    int h = n >> 6, d = n & 63;
                    dst[(((size_t)(bb * NH + h)) * SQ + ss) * HD + d] =
                        __uint_as_float(f2tf(v));
                }
            }
        }
    }
}

// Output projection with entropy-gated scale. grid (32, 8).
__global__ void __launch_bounds__(256) out_gemm(const float* __restrict__ ow,
                                                const float* __restrict__ ob,
                                                float* __restrict__ out,
                                                float c_full) {
    extern __shared__ float smf[];
    float* As = smf;
    float* Bs = smf + 2 * GSTRIDE;
    const int m0 = blockIdx.x * 128, n0 = blockIdx.y * 128;

    float acc[4][4][4] = {};
    gemm_core_tf32(g_base, ow, m0, n0, As, Bs, acc);

    float avg_ent = g_ent * (1.0f / 65536.0f);
    float scale = (avg_ent < 0.2f) ? 1.0f : c_full;

    const int t = threadIdx.x, w = t >> 5, lane = t & 31;
    const int g = lane >> 2, tig = lane & 3;
    const int wm = w >> 2, wn = w & 3;
#pragma unroll
    for (int mf = 0; mf < 4; mf++) {
#pragma unroll
        for (int e = 0; e < 2; e++) {
            int m = m0 + wm * 64 + mf * 16 + g + e * 8;
#pragma unroll
            for (int nf = 0; nf < 4; nf++) {
#pragma unroll
                for (int j = 0; j < 2; j++) {
                    int n = n0 + wn * 32 + nf * 8 + 2 * tig + j;
                    out[(size_t)m * HID + n] = fmaf(scale, acc[mf][nf][e * 2 + j], ob[n]);
                }
            }
        }
    }
}

// ---------------------------------------------------------------------------
// TF32 flash attention. grid (SQ/128 = 16, B*H = 32). 256 threads, 8 warps.
// Warp w owns q-rows [w*16, w*16+16). Key tiles of 64. Online softmax in regs.
// ---------------------------------------------------------------------------
#define AP 68
#define ATTN_SMEM_BYTES ((2 * 64 * AP + 128 * AP + 64 + 8) * 4)

__global__ void __launch_bounds__(256) attn_tf32(const int* __restrict__ amask) {
    extern __shared__ float smf[];
    float* Kt   = smf;                       // [64][AP]
    float* Vt   = smf + 64 * AP;             // [64][AP]
    float* Ps   = smf + 2 * 64 * AP;         // [128][AP] Q-staging then P (warp-private rows)
    float* kmsk = smf + 2 * 64 * AP + 128 * AP;  // [64]
    float* wred = kmsk + 64;                 // [8]

    const int t = threadIdx.x, w = t >> 5, lane = t & 31;
    const int g = lane >> 2, tig = lane & 3;
    const int bh = blockIdx.y, q0 = blockIdx.x * 128;
    const int bb = bh >> 4, hh = bh & 15;

    const float* qp = g_q + ((size_t)bh * SQ + q0) * HD;
    const float* kp = g_k + (size_t)bh * SQ * HD;
    const float* vp = g_v + (size_t)bh * SQ * HD;

    // Stage Q to smem, then load A-fragments (values already tf32-rounded).
    {
        int r = t >> 4, c4 = (t & 15) << 2;
#pragma unroll
        for (int p = 0; p < 8; p++)
            *(float4*)(Ps + (r + p * 16) * AP + c4) =
                *(const float4*)(qp + (size_t)(r + p * 16) * HD + c4);
    }
    __syncthreads();
    uint32_t qf[8][4];
#pragma unroll
    for (int kf = 0; kf < 8; kf++) {
        const float* p0 = Ps + (w * 16 + g) * AP + kf * 8 + tig;
        qf[kf][0] = __float_as_uint(p0[0]);
        qf[kf][1] = __float_as_uint(p0[8 * AP]);
        qf[kf][2] = __float_as_uint(p0[4]);
        qf[kf][3] = __float_as_uint(p0[8 * AP + 4]);
    }

    float o[8][4] = {};
    float m0r = -1e30f, m1r = -1e30f;
    float l0 = 0.f, l1 = 0.f, t0 = 0.f, t1 = 0.f;

    for (int kt = 0; kt < 32; kt++) {
        __syncthreads();  // protect Kt/Vt (and Ps Q-staging on first iter)
        {
            int r = t >> 4, c4 = (t & 15) << 2;
#pragma unroll
            for (int p = 0; p < 4; p++) {
                int rr = r + p * 16;
                *(float4*)(Kt + rr * AP + c4) =
                    *(const float4*)(kp + (size_t)(kt * 64 + rr) * HD + c4);
                *(float4*)(Vt + rr * AP + c4) =
                    *(const float4*)(vp + (size_t)(kt * 64 + rr) * HD + c4);
            }
            if (t < 64) kmsk[t] = amask[bb * SQ + kt * 64 + t] ? 0.f : -1e30f;
        }
        __syncthreads();

        // S = Q @ K^T : 8 n-frags over 64 keys
        float sc[8][4] = {};
#pragma unroll
        for (int kf = 0; kf < 8; kf++) {
#pragma unroll
            for (int nf = 0; nf < 8; nf++) {
                const float* p0 = Kt + (nf * 8 + g) * AP + kf * 8 + tig;
                uint32_t b0 = __float_as_uint(p0[0]);
                uint32_t b1 = __float_as_uint(p0[4]);
                mma8(sc[nf], qf[kf][0], qf[kf][1], qf[kf][2], qf[kf][3], b0, b1);
            }
        }

        // mask + online softmax (rows g and g+8 of this thread)
        float mx0 = -1e30f, mx1 = -1e30f;
#pragma unroll
        for (int nf = 0; nf < 8; nf++) {
            float k0 = kmsk[nf * 8 + 2 * tig], k1 = kmsk[nf * 8 + 2 * tig + 1];
            sc[nf][0] += k0; sc[nf][1] += k1; sc[nf][2] += k0; sc[nf][3] += k1;
            mx0 = fmaxf(mx0, fmaxf(sc[nf][0], sc[nf][1]));
            mx1 = fmaxf(mx1, fmaxf(sc[nf][2], sc[nf][3]));
        }
        mx0 = fmaxf(mx0, __shfl_xor_sync(0xffffffffu, mx0, 1));
        mx0 = fmaxf(mx0, __shfl_xor_sync(0xffffffffu, mx0, 2));
        mx1 = fmaxf(mx1, __shfl_xor_sync(0xffffffffu, mx1, 1));
        mx1 = fmaxf(mx1, __shfl_xor_sync(0xffffffffu, mx1, 2));
        float mn0 = fmaxf(m0r, mx0), mn1 = fmaxf(m1r, mx1);
        float sf0 = fexp(m0r - mn0), sf1 = fexp(m1r - mn1);
        m0r = mn0; m1r = mn1;

        float la0 = 0.f, la1 = 0.f, ta0 = 0.f, ta1 = 0.f;
        float* prow0 = Ps + (w * 16 + g) * AP;
        float* prow1 = Ps + (w * 16 + g + 8) * AP;
#pragma unroll
        for (int nf = 0; nf < 8; nf++) {
            float x00 = fmaxf(sc[nf][0] - mn0, -80.f);
            float x01 = fmaxf(sc[nf][1] - mn0, -80.f);
            float x10 = fmaxf(sc[nf][2] - mn1, -80.f);
            float x11 = fmaxf(sc[nf][3] - mn1, -80.f);
            float p00 = fexp(x00), p01 = fexp(x01);
            float p10 = fexp(x10), p11 = fexp(x11);
            la0 += p00 + p01; la1 += p10 + p11;
            ta0 = fmaf(p00, x00, ta0); ta0 = fmaf(p01, x01, ta0);
            ta1 = fmaf(p10, x10, ta1); ta1 = fmaf(p11, x11, ta1);
            int c = nf * 8 + 2 * tig;
            prow0[c]     = __uint_as_float(f2tf(p00));
            prow0[c + 1] = __uint_as_float(f2tf(p01));
            prow1[c]     = __uint_as_float(f2tf(p10));
            prow1[c + 1] = __uint_as_float(f2tf(p11));
        }
        // ROUND-4 FIX: la/ta are per-thread partial row sums (16 of 64 cols).
        // Reduce across the 4 threads (tig) of the MMA quad so l/t are true
        // row sums — without this, O is normalized by ~l/4 (rel_err == 3.0).
        la0 += __shfl_xor_sync(0xffffffffu, la0, 1);
        la0 += __shfl_xor_sync(0xffffffffu, la0, 2);
        la1 += __shfl_xor_sync(0xffffffffu, la1, 1);
        la1 += __shfl_xor_sync(0xffffffffu, la1, 2);
        ta0 += __shfl_xor_sync(0xffffffffu, ta0, 1);
        ta0 += __shfl_xor_sync(0xffffffffu, ta0, 2);
        ta1 += __shfl_xor_sync(0xffffffffu, ta1, 1);
        ta1 += __shfl_xor_sync(0xffffffffu, ta1, 2);

        l0 = fmaf(l0, sf0, la0);
        l1 = fmaf(l1, sf1, la1);
        t0 = t0 * sf0 + ta0 + mn0 * la0;
        t1 = t1 * sf1 + ta1 + mn1 * la1;
#pragma unroll
        for (int nf = 0; nf < 8; nf++) {
            o[nf][0] *= sf0; o[nf][1] *= sf0;
            o[nf][2] *= sf1; o[nf][3] *= sf1;
        }
        __syncwarp();  // P visible across the warp

        // O += P @ V
#pragma unroll
        for (int kf = 0; kf < 8; kf++) {
            const float* a0p = Ps + (w * 16 + g) * AP + kf * 8 + tig;
            const float* a1p = Ps + (w * 16 + g + 8) * AP + kf * 8 + tig;
            uint32_t a0 = __float_as_uint(a0p[0]);
            uint32_t a1 = __float_as_uint(a1p[0]);
            uint32_t a2 = __float_as_uint(a0p[4]);
            uint32_t a3 = __float_as_uint(a1p[4]);
#pragma unroll
            for (int nf = 0; nf < 8; nf++) {
                const float* b0p = Vt + (kf * 8 + tig) * AP + nf * 8 + g;
                uint32_t b0 = __float_as_uint(b0p[0]);
                uint32_t b1 = __float_as_uint(b0p[4 * AP]);
                mma8(o[nf], a0, a1, a2, a3, b0, b1);
            }
        }
    }

    // Write normalized O to merged [B,S,HID]
    float inv0 = 1.0f / l0, inv1 = 1.0f / l1;
    float* ob0 = g_base + ((size_t)(bb * SQ + q0 + w * 16 + g)) * HID + hh * HD;
    float* ob1 = ob0 + 8 * HID;
#pragma unroll
    for (int nf = 0; nf < 8; nf++) {
        int c = nf * 8 + 2 * tig;
        ob0[c]     = o[nf][0] * inv0;
        ob0[c + 1] = o[nf][1] * inv0;
        ob1[c]     = o[nf][2] * inv1;
        ob1[c + 1] = o[nf][3] * inv1;
    }

    // Entropy: H_row = m + log(l) - T/l (only tig==0 lanes hold unique rows)
    float h = 0.f;
    if (tig == 0)
        h = (m0r + __logf(l0) - t0 * inv0) + (m1r + __logf(l1) - t1 * inv1);
#pragma unroll
    for (int off = 16; off; off >>= 1)
        h += __shfl_xor_sync(0xffffffffu, h, off);
    if (lane == 0) wred[w] = h;
    __syncthreads();
    if (t == 0) {
        float s = 0.f;
#pragma unroll
        for (int i = 0; i < 8; i++) s += wred[i];
        atomicAdd(&g_ent, s);
    }
}

extern "C" void kernel_launch(void* const* d_in, const int* in_sizes, int n_in,
                              void* d_out, int out_size) {
    const float* x  = (const float*)d_in[0];
    const float* qw = (const float*)d_in[1];
    const float* qb = (const float*)d_in[2];
    const float* kw = (const float*)d_in[3];
    const float* kb = (const float*)d_in[4];
    const float* vw = (const float*)d_in[5];
    const float* vb = (const float*)d_in[6];
    const float* ow = (const float*)d_in[7];
    const float* ob = (const float*)d_in[8];
    const int* amask = (const int*)d_in[9];
    float* out = (float*)d_out;

    // Collapse the deterministic blend loop: full = c * base
    double c = 1.0;
    for (int i = 1; i < 10; i++) {
        double blend = 1.0 / (1.0 + exp(-(double)i / 10.0));
        double rs = 0.5 + 0.5 * blend;
        c = (1.0 - blend) * c + blend * rs;
    }

    const int gemm_smem = 2 * 2 * GSTRIDE * 4;  // 73728 bytes
    cudaFuncSetAttribute(qkv_gemm, cudaFuncAttributeMaxDynamicSharedMemorySize, gemm_smem);
    cudaFuncSetAttribute(out_gemm, cudaFuncAttributeMaxDynamicSharedMemorySize, gemm_smem);
    cudaFuncSetAttribute(attn_tf32, cudaFuncAttributeMaxDynamicSharedMemorySize, ATTN_SMEM_BYTES);

    init_kernel<<<1, 1>>>();
    qkv_gemm<<<dim3(32, 8, 3), 256, gemm_smem>>>(x, qw, qb, kw, kb, vw, vb);
    attn_tf32<<<dim3(16, 32), 256, ATTN_SMEM_BYTES>>>(amask);
    out_gemm<<<dim3(32, 8), 256, gemm_smem>>>(ow, ob, out, (float)c);
}

// round 8
// speedup vs baseline: 3.4424x; 1.1322x over previous
#include <cuda_runtime.h>
#include <math.h>
#include <stdint.h>

#define NTOK 4096
#define HID  1024
#define SQ   2048
#define NH   16
#define HD   64
#define PRIME_SCALE_F 0.047245559126404574f  /* 1/sqrt(7*64) */

// Scratch (allocation-free rule: device globals)
__device__ float g_q[NTOK * HID];       // tf32-rounded, [B,H,S,D]
__device__ float g_k[NTOK * HID];
__device__ float g_v[NTOK * HID];
__device__ float g_base[NTOK * HID];    // tf32-rounded, [B,S,HID]
__device__ float g_xr[NTOK * HID];      // tf32-rounded input x
__device__ float g_wr[4 * HID * HID];   // tf32-rounded qw,kw,vw,ow
__device__ float g_ent;

__global__ void init_kernel() { g_ent = 0.0f; }

// ---------------------------------------------------------------------------
// helpers
// ---------------------------------------------------------------------------
__device__ __forceinline__ uint32_t f2tf(float f) {
    uint32_t r;
    asm("cvt.rna.tf32.f32 %0, %1;" : "=r"(r) : "f"(f));
    return r;
}
__device__ __forceinline__ float f2tff(float f) {
    return __uint_as_float(f2tf(f));
}

__device__ __forceinline__ uint32_t smem_u32(const void* p) {
    return (uint32_t)__cvta_generic_to_shared(p);
}
#define CPA16(dst_u32, src_ptr) \
    asm volatile("cp.async.ca.shared.global [%0], [%1], 16;" :: "r"(dst_u32), "l"(src_ptr))
#define CPCOMMIT() asm volatile("cp.async.commit_group;")
#define CPWAIT0()  asm volatile("cp.async.wait_group 0;")

__device__ __forceinline__ void mma8(float* c,
                                     uint32_t a0, uint32_t a1, uint32_t a2, uint32_t a3,
                                     uint32_t b0, uint32_t b1) {
    asm volatile(
        "mma.sync.aligned.m16n8k8.row.col.f32.tf32.tf32.f32 "
        "{%0,%1,%2,%3},{%4,%5,%6,%7},{%8,%9},{%0,%1,%2,%3};"
        : "+f"(c[0]), "+f"(c[1]), "+f"(c[2]), "+f"(c[3])
        : "r"(a0), "r"(a1), "r"(a2), "r"(a3), "r"(b0), "r"(b1));
}

// exp(x) on the FMA pipe (no MUFU). ~1e-7 rel err.
__device__ __forceinline__ float fexp(float x) {
    x = fmaxf(x, -80.0f);
    float y = x * 1.4426950408889634f;
    float z = y + 12582912.0f;
    int   n = __float_as_int(z) << 23;
    float f = y - (z - 12582912.0f);
    float p = 1.5403531e-4f;
    p = fmaf(p, f, 1.3333558e-3f);
    p = fmaf(p, f, 9.6181291e-3f);
    p = fmaf(p, f, 5.5504109e-2f);
    p = fmaf(p, f, 2.4022651e-1f);
    p = fmaf(p, f, 6.9314718e-1f);
    p = fmaf(p, f, 1.0f);
    return __int_as_float(__float_as_int(p) + n);
}

// ---------------------------------------------------------------------------
// Prep: round x and all 4 weight matrices to tf32 once.
// i ranges over float4 slots: 1M (x) + 4*256K (weights) = 2M.
// ---------------------------------------------------------------------------
#define N4X (NTOK * HID / 4)
#define N4W (HID * HID / 4)

__global__ void __launch_bounds__(256) prep_kernel(
    const float* __restrict__ x,  const float* __restrict__ qw,
    const float* __restrict__ kw, const float* __restrict__ vw,
    const float* __restrict__ ow) {
    int i = blockIdx.x * 256 + threadIdx.x;
    const float4* s;
    float4* d;
    if (i < N4X) {
        s = (const float4*)x + i;
        d = (float4*)g_xr + i;
    } else {
        int j = i - N4X;
        int wsel = j >> 18;          // / N4W (262144)
        int k = j & (N4W - 1);
        const float* ws = wsel == 0 ? qw : wsel == 1 ? kw : wsel == 2 ? vw : ow;
        s = (const float4*)ws + k;
        d = (float4*)g_wr + ((size_t)wsel << 18) + k;
    }
    float4 v = *s;
    v.x = f2tff(v.x); v.y = f2tff(v.y); v.z = f2tff(v.z); v.w = f2tff(v.w);
    *d = v;
}

// ---------------------------------------------------------------------------
// TF32 GEMM core (pre-rounded inputs): C[128x128] = A * B^T, K = 1024.
// cp.async double-buffered k-slices of 32; one __syncthreads per slice.
// ---------------------------------------------------------------------------
#define GP 36
#define GSTRIDE (128 * GP)

__device__ __forceinline__ void gemm_core(
    const float* __restrict__ A, const float* __restrict__ B,
    int m0, int n0, float* As, float* Bs, float acc[4][4][4]) {
    const int t = threadIdx.x;
    const int w = t >> 5, lane = t & 31;
    const int wm = w >> 2, wn = w & 3;
    const int g = lane >> 2, tig = lane & 3;
    const int lr = t >> 3;           // 0..31
    const int lc = (t & 7) << 2;     // 0,4,..,28

    const float* ga = A + (size_t)(m0 + lr) * HID + lc;
    const float* gb = B + (size_t)(n0 + lr) * HID + lc;
    const uint32_t sa = smem_u32(As);
    const uint32_t sb = smem_u32(Bs);

    // stage k-slice s into buffer buf
#define GEMM_STAGE(s, buf) do {                                               \
        uint32_t off = (uint32_t)((buf) * GSTRIDE + lr * GP + lc) * 4u;       \
        _Pragma("unroll")                                                     \
        for (int p = 0; p < 4; p++) {                                         \
            CPA16(sa + off + p * (32 * GP * 4), ga + (s) * 32 + (size_t)p * 32 * HID); \
            CPA16(sb + off + p * (32 * GP * 4), gb + (s) * 32 + (size_t)p * 32 * HID); \
        }                                                                     \
    } while (0)

    GEMM_STAGE(0, 0);
    CPCOMMIT();

    for (int s = 0; s < 32; s++) {
        CPWAIT0();
        __syncthreads();
        if (s < 31) {
            GEMM_STAGE(s + 1, (s + 1) & 1);
            CPCOMMIT();
        }
        const float* Ac = As + (s & 1) * GSTRIDE;
        const float* Bc = Bs + (s & 1) * GSTRIDE;
#pragma unroll
        for (int kf = 0; kf < 4; kf++) {
            uint32_t af[4][4], bf[4][2];
#pragma unroll
            for (int mf = 0; mf < 4; mf++) {
                const float* p0 = Ac + (wm * 64 + mf * 16 + g) * GP + kf * 8 + tig;
                af[mf][0] = __float_as_uint(p0[0]);
                af[mf][1] = __float_as_uint(p0[8 * GP]);
                af[mf][2] = __float_as_uint(p0[4]);
                af[mf][3] = __float_as_uint(p0[8 * GP + 4]);
            }
#pragma unroll
            for (int nf = 0; nf < 4; nf++) {
                const float* p0 = Bc + (wn * 32 + nf * 8 + g) * GP + kf * 8 + tig;
                bf[nf][0] = __float_as_uint(p0[0]);
                bf[nf][1] = __float_as_uint(p0[4]);
            }
#pragma unroll
            for (int mf = 0; mf < 4; mf++)
#pragma unroll
                for (int nf = 0; nf < 4; nf++)
                    mma8(acc[mf][nf], af[mf][0], af[mf][1], af[mf][2], af[mf][3],
                         bf[nf][0], bf[nf][1]);
        }
    }
#undef GEMM_STAGE
}

// QKV projection. grid (32, 8, 3). Writes tf32-rounded head-major [B,H,S,D].
__global__ void __launch_bounds__(256) qkv_gemm(
    const float* __restrict__ qb, const float* __restrict__ kb,
    const float* __restrict__ vb) {
    extern __shared__ float smf[];
    float* As = smf;
    float* Bs = smf + 2 * GSTRIDE;
    const int m0 = blockIdx.x * 128, n0 = blockIdx.y * 128;
    const float* bias; float* dst; float scl;
    const float* W = g_wr + (size_t)blockIdx.z * HID * HID;
    if (blockIdx.z == 0)      { bias = qb; dst = g_q; scl = PRIME_SCALE_F; }
    else if (blockIdx.z == 1) { bias = kb; dst = g_k; scl = 1.0f; }
    else                      { bias = vb; dst = g_v; scl = 1.0f; }

    float acc[4][4][4] = {};
    gemm_core(g_xr, W, m0, n0, As, Bs, acc);

    const int t = threadIdx.x, w = t >> 5, lane = t & 31;
    const int g = lane >> 2, tig = lane & 3;
    const int wm = w >> 2, wn = w & 3;
#pragma unroll
    for (int mf = 0; mf < 4; mf++) {
#pragma unroll
        for (int e = 0; e < 2; e++) {
            int m = m0 + wm * 64 + mf * 16 + g + e * 8;
            int bb = m >> 11, ss = m & 2047;
#pragma unroll
            for (int nf = 0; nf < 4; nf++) {
#pragma unroll
                for (int j = 0; j < 2; j++) {
                    int n = n0 + wn * 32 + nf * 8 + 2 * tig + j;
                    float v = (acc[mf][nf][e * 2 + j] + bias[n]) * scl;
                    int h = n >> 6, d = n & 63;
                    dst[(((size_t)(bb * NH + h)) * SQ + ss) * HD + d] = f2tff(v);
                }
            }
        }
    }
}

// Output projection with entropy-gated scale. grid (32, 8).
__global__ void __launch_bounds__(256) out_gemm(const float* __restrict__ ob,
                                                float* __restrict__ out,
                                                float c_full) {
    extern __shared__ float smf[];
    float* As = smf;
    float* Bs = smf + 2 * GSTRIDE;
    const int m0 = blockIdx.x * 128, n0 = blockIdx.y * 128;

    float acc[4][4][4] = {};
    gemm_core(g_base, g_wr + 3 * (size_t)HID * HID, m0, n0, As, Bs, acc);

    float avg_ent = g_ent * (1.0f / 65536.0f);
    float scale = (avg_ent < 0.2f) ? 1.0f : c_full;

    const int t = threadIdx.x, w = t >> 5, lane = t & 31;
    const int g = lane >> 2, tig = lane & 3;
    const int wm = w >> 2, wn = w & 3;
#pragma unroll
    for (int mf = 0; mf < 4; mf++) {
#pragma unroll
        for (int e = 0; e < 2; e++) {
            int m = m0 + wm * 64 + mf * 16 + g + e * 8;
#pragma unroll
            for (int nf = 0; nf < 4; nf++) {
#pragma unroll
                for (int j = 0; j < 2; j++) {
                    int n = n0 + wn * 32 + nf * 8 + 2 * tig + j;
                    out[(size_t)m * HID + n] = fmaf(scale, acc[mf][nf][e * 2 + j], ob[n]);
                }
            }
        }
    }
}

// ---------------------------------------------------------------------------
// TF32 flash attention. grid (SQ/128 = 16, B*H = 32). 256 threads, 8 warps.
// cp.async double-buffered K/V/mask; ONE __syncthreads per key-tile.
// l/t kept as per-thread partials across all tiles; reduced once at the end.
// ---------------------------------------------------------------------------
#define AP 68
#define KVT (64 * AP)                       // floats per K or V tile
#define ATTN_SMEM_BYTES ((4 * KVT + 128 * AP) * 4 + 2 * 64 * 4 + 64)

__global__ void __launch_bounds__(256, 2) attn_tf32(const int* __restrict__ amask) {
    extern __shared__ float smf[];
    float* Kb = smf;                         // [2][64][AP]
    float* Vb = smf + 2 * KVT;               // [2][64][AP]
    float* Ps = smf + 4 * KVT;               // [128][AP] Q-staging then P
    int*   mk = (int*)(smf + 4 * KVT + 128 * AP);   // [2][64]
    float* wred = (float*)(mk + 2 * 64);     // [8]

    const int t = threadIdx.x, w = t >> 5, lane = t & 31;
    const int g = lane >> 2, tig = lane & 3;
    const int bh = blockIdx.y, q0 = blockIdx.x * 128;
    const int bb = bh >> 4, hh = bh & 15;

    const float* qp = g_q + ((size_t)bh * SQ + q0) * HD;
    const float* kp = g_k + (size_t)bh * SQ * HD;
    const float* vp = g_v + (size_t)bh * SQ * HD;
    const int*   mp = amask + bb * SQ;

    const uint32_t skb = smem_u32(Kb);
    const uint32_t svb = smem_u32(Vb);
    const uint32_t smk = smem_u32(mk);
    const int sr  = t >> 4;                  // 0..15
    const int sc4 = (t & 15) << 2;           // 0,4,..,60

#define ATTN_STAGE(kt, buf) do {                                              \
        uint32_t off = (uint32_t)((buf) * KVT + sr * AP + sc4) * 4u;          \
        _Pragma("unroll")                                                     \
        for (int p = 0; p < 4; p++) {                                         \
            int rr = sr + p * 16;                                             \
            CPA16(skb + off + p * (16 * AP * 4),                              \
                  kp + (size_t)((kt) * 64 + rr) * HD + sc4);                  \
            CPA16(svb + off + p * (16 * AP * 4),                              \
                  vp + (size_t)((kt) * 64 + rr) * HD + sc4);                  \
        }                                                                     \
        if (t < 16)                                                           \
            CPA16(smk + ((buf) * 64 + t * 4) * 4u, mp + (kt) * 64 + t * 4);   \
    } while (0)

    // Stage Q into Ps (plain loads, once), then fragments.
    {
#pragma unroll
        for (int p = 0; p < 8; p++)
            *(float4*)(Ps + (sr + p * 16) * AP + sc4) =
                *(const float4*)(qp + (size_t)(sr + p * 16) * HD + sc4);
    }
    ATTN_STAGE(0, 0);
    CPCOMMIT();
    __syncthreads();
    uint32_t qf[8][4];
#pragma unroll
    for (int kf = 0; kf < 8; kf++) {
        const float* p0 = Ps + (w * 16 + g) * AP + kf * 8 + tig;
        qf[kf][0] = __float_as_uint(p0[0]);
        qf[kf][1] = __float_as_uint(p0[8 * AP]);
        qf[kf][2] = __float_as_uint(p0[4]);
        qf[kf][3] = __float_as_uint(p0[8 * AP + 4]);
    }

    float o[8][4] = {};
    float m0r = -1e30f, m1r = -1e30f;
    float l0 = 0.f, l1 = 0.f, t0 = 0.f, t1 = 0.f;   // per-thread partials

    for (int kt = 0; kt < 32; kt++) {
        CPWAIT0();
        __syncthreads();            // buf[kt&1] ready; all warps done with kt-1
        if (kt < 31) {
            ATTN_STAGE(kt + 1, (kt + 1) & 1);
            CPCOMMIT();
        }
        const float* Kt = Kb + (kt & 1) * KVT;
        const float* Vt = Vb + (kt & 1) * KVT;
        const int*   mc = mk + (kt & 1) * 64;

        // S = Q @ K^T
        float sc[8][4] = {};
#pragma unroll
        for (int kf = 0; kf < 8; kf++) {
#pragma unroll
            for (int nf = 0; nf < 8; nf++) {
                const float* p0 = Kt + (nf * 8 + g) * AP + kf * 8 + tig;
                uint32_t b0 = __float_as_uint(p0[0]);
                uint32_t b1 = __float_as_uint(p0[4]);
                mma8(sc[nf], qf[kf][0], qf[kf][1], qf[kf][2], qf[kf][3], b0, b1);
            }
        }

        // mask + row max (quad reduction)
        float mx0 = -1e30f, mx1 = -1e30f;
#pragma unroll
        for (int nf = 0; nf < 8; nf++) {
            float k0 = mc[nf * 8 + 2 * tig]     ? 0.f : -1e30f;
            float k1 = mc[nf * 8 + 2 * tig + 1] ? 0.f : -1e30f;
            sc[nf][0] += k0; sc[nf][1] += k1; sc[nf][2] += k0; sc[nf][3] += k1;
            mx0 = fmaxf(mx0, fmaxf(sc[nf][0], sc[nf][1]));
            mx1 = fmaxf(mx1, fmaxf(sc[nf][2], sc[nf][3]));
        }
        mx0 = fmaxf(mx0, __shfl_xor_sync(0xffffffffu, mx0, 1));
        mx0 = fmaxf(mx0, __shfl_xor_sync(0xffffffffu, mx0, 2));
        mx1 = fmaxf(mx1, __shfl_xor_sync(0xffffffffu, mx1, 1));
        mx1 = fmaxf(mx1, __shfl_xor_sync(0xffffffffu, mx1, 2));
        float mn0 = fmaxf(m0r, mx0), mn1 = fmaxf(m1r, mx1);
        float sf0 = fexp(m0r - mn0), sf1 = fexp(m1r - mn1);
        m0r = mn0; m1r = mn1;

        // exp + P store (per-thread partial l/t; NO quad reduction here)
        float la0 = 0.f, la1 = 0.f, ta0 = 0.f, ta1 = 0.f;
        float* prow0 = Ps + (w * 16 + g) * AP;
        float* prow1 = Ps + (w * 16 + g + 8) * AP;
#pragma unroll
        for (int nf = 0; nf < 8; nf++) {
            float x00 = fmaxf(sc[nf][0] - mn0, -80.f);
            float x01 = fmaxf(sc[nf][1] - mn0, -80.f);
            float x10 = fmaxf(sc[nf][2] - mn1, -80.f);
            float x11 = fmaxf(sc[nf][3] - mn1, -80.f);
            float p00 = fexp(x00), p01 = fexp(x01);
            float p10 = fexp(x10), p11 = fexp(x11);
            la0 += p00 + p01; la1 += p10 + p11;
            ta0 = fmaf(p00, x00, ta0); ta0 = fmaf(p01, x01, ta0);
            ta1 = fmaf(p10, x10, ta1); ta1 = fmaf(p11, x11, ta1);
            int c = nf * 8 + 2 * tig;
            *(float2*)&prow0[c] = make_float2(f2tff(p00), f2tff(p01));
            *(float2*)&prow1[c] = make_float2(f2tff(p10), f2tff(p11));
        }
        l0 = fmaf(l0, sf0, la0);
        l1 = fmaf(l1, sf1, la1);
        t0 = t0 * sf0 + ta0 + mn0 * la0;
        t1 = t1 * sf1 + ta1 + mn1 * la1;
#pragma unroll
        for (int nf = 0; nf < 8; nf++) {
            o[nf][0] *= sf0; o[nf][1] *= sf0;
            o[nf][2] *= sf1; o[nf][3] *= sf1;
        }
        __syncwarp();  // P rows are warp-private: warp-sync suffices

        // O += P @ V
#pragma unroll
        for (int kf = 0; kf < 8; kf++) {
            const float* a0p = Ps + (w * 16 + g) * AP + kf * 8 + tig;
            const float* a1p = Ps + (w * 16 + g + 8) * AP + kf * 8 + tig;
            uint32_t a0 = __float_as_uint(a0p[0]);
            uint32_t a1 = __float_as_uint(a1p[0]);
            uint32_t a2 = __float_as_uint(a0p[4]);
            uint32_t a3 = __float_as_uint(a1p[4]);
#pragma unroll
            for (int nf = 0; nf < 8; nf++) {
                const float* b0p = Vt + (kf * 8 + tig) * AP + nf * 8 + g;
                uint32_t b0 = __float_as_uint(b0p[0]);
                uint32_t b1 = __float_as_uint(b0p[4 * AP]);
                mma8(o[nf], a0, a1, a2, a3, b0, b1);
            }
        }
        __syncwarp();  // all lanes done reading P before next iter overwrites
    }

    // Final quad reductions of l/t (deferred from the loop)
    l0 += __shfl_xor_sync(0xffffffffu, l0, 1);
    l0 += __shfl_xor_sync(0xffffffffu, l0, 2);
    l1 += __shfl_xor_sync(0xffffffffu, l1, 1);
    l1 += __shfl_xor_sync(0xffffffffu, l1, 2);
    t0 += __shfl_xor_sync(0xffffffffu, t0, 1);
    t0 += __shfl_xor_sync(0xffffffffu, t0, 2);
    t1 += __shfl_xor_sync(0xffffffffu, t1, 1);
    t1 += __shfl_xor_sync(0xffffffffu, t1, 2);

    // Write normalized O (tf32-rounded so out_gemm skips conversion)
    float inv0 = 1.0f / l0, inv1 = 1.0f / l1;
    float* ob0 = g_base + ((size_t)(bb * SQ + q0 + w * 16 + g)) * HID + hh * HD;
    float* ob1 = ob0 + 8 * HID;
#pragma unroll
    for (int nf = 0; nf < 8; nf++) {
        int c = nf * 8 + 2 * tig;
        ob0[c]     = f2tff(o[nf][0] * inv0);
        ob0[c + 1] = f2tff(o[nf][1] * inv0);
        ob1[c]     = f2tff(o[nf][2] * inv1);
        ob1[c + 1] = f2tff(o[nf][3] * inv1);
    }

    // Entropy: H_row = m + log(l) - T/l (tig==0 lanes hold unique rows)
    float h = 0.f;
    if (tig == 0)
        h = (m0r + __logf(l0) - t0 * inv0) + (m1r + __logf(l1) - t1 * inv1);
#pragma unroll
    for (int off = 16; off; off >>= 1)
        h += __shfl_xor_sync(0xffffffffu, h, off);
    if (lane == 0) wred[w] = h;
    __syncthreads();
    if (t == 0) {
        float s = 0.f;
#pragma unroll
        for (int i = 0; i < 8; i++) s += wred[i];
        atomicAdd(&g_ent, s);
    }
#undef ATTN_STAGE
}

extern "C" void kernel_launch(void* const* d_in, const int* in_sizes, int n_in,
                              void* d_out, int out_size) {
    const float* x  = (const float*)d_in[0];
    const float* qw = (const float*)d_in[1];
    const float* qb = (const float*)d_in[2];
    const float* kw = (const float*)d_in[3];
    const float* kb = (const float*)d_in[4];
    const float* vw = (const float*)d_in[5];
    const float* vb = (const float*)d_in[6];
    const float* ow = (const float*)d_in[7];
    const float* ob = (const float*)d_in[8];
    const int* amask = (const int*)d_in[9];
    float* out = (float*)d_out;

    // Collapse the deterministic blend loop: full = c * base
    double c = 1.0;
    for (int i = 1; i < 10; i++) {
        double blend = 1.0 / (1.0 + exp(-(double)i / 10.0));
        double rs = 0.5 + 0.5 * blend;
        c = (1.0 - blend) * c + blend * rs;
    }

    const int gemm_smem = 2 * 2 * GSTRIDE * 4;  // 73728 bytes
    cudaFuncSetAttribute(qkv_gemm, cudaFuncAttributeMaxDynamicSharedMemorySize, gemm_smem);
    cudaFuncSetAttribute(out_gemm, cudaFuncAttributeMaxDynamicSharedMemorySize, gemm_smem);
    cudaFuncSetAttribute(attn_tf32, cudaFuncAttributeMaxDynamicSharedMemorySize, ATTN_SMEM_BYTES);

    init_kernel<<<1, 1>>>();
    prep_kernel<<<(N4X + 4 * N4W + 255) / 256, 256>>>(x, qw, kw, vw, ow);
    qkv_gemm<<<dim3(32, 8, 3), 256, gemm_smem>>>(qb, kb, vb);
    attn_tf32<<<dim3(16, 32), 256, ATTN_SMEM_BYTES>>>(amask);
    out_gemm<<<dim3(32, 8), 256, gemm_smem>>>(ob, out, (float)c);
}

// round 10
// speedup vs baseline: 3.8976x; 1.1322x over previous
#include <cuda_runtime.h>
#include <math.h>
#include <stdint.h>

#define NTOK 4096
#define HID  1024
#define SQ   2048
#define NH   16
#define HD   64
#define PRIME_SCALE_F 0.047245559126404574f  /* 1/sqrt(7*64) */

// Scratch (allocation-free rule: device globals)
__device__ float g_q[NTOK * HID];       // tf32-rounded, [B,H,S,D]
__device__ float g_k[NTOK * HID];       // tf32-rounded, [B,H,S,D]
__device__ float g_v[NTOK * HID];       // tf32-rounded, TRANSPOSED [B,H,D,S]
__device__ float g_base[NTOK * HID];    // tf32-rounded, [B,S,HID]
__device__ float g_xr[NTOK * HID];      // tf32-rounded input x
__device__ float g_wr[4 * HID * HID];   // tf32-rounded qw,kw,vw,ow
__device__ float g_ent;

__global__ void init_kernel() { g_ent = 0.0f; }

// ---------------------------------------------------------------------------
// helpers
// ---------------------------------------------------------------------------
__device__ __forceinline__ uint32_t f2tf(float f) {
    uint32_t r;
    asm("cvt.rna.tf32.f32 %0, %1;" : "=r"(r) : "f"(f));
    return r;
}
__device__ __forceinline__ float f2tff(float f) {
    return __uint_as_float(f2tf(f));
}

__device__ __forceinline__ uint32_t smem_u32(const void* p) {
    return (uint32_t)__cvta_generic_to_shared(p);
}
#define CPA16(dst_u32, src_ptr) \
    asm volatile("cp.async.ca.shared.global [%0], [%1], 16;" :: "r"(dst_u32), "l"(src_ptr))
#define CPCOMMIT() asm volatile("cp.async.commit_group;")
#define CPWAIT0()  asm volatile("cp.async.wait_group 0;")

__device__ __forceinline__ void mma8(float* c,
                                     uint32_t a0, uint32_t a1, uint32_t a2, uint32_t a3,
                                     uint32_t b0, uint32_t b1) {
    asm volatile(
        "mma.sync.aligned.m16n8k8.row.col.f32.tf32.tf32.f32 "
        "{%0,%1,%2,%3},{%4,%5,%6,%7},{%8,%9},{%0,%1,%2,%3};"
        : "+f"(c[0]), "+f"(c[1]), "+f"(c[2]), "+f"(c[3])
        : "r"(a0), "r"(a1), "r"(a2), "r"(a3), "r"(b0), "r"(b1));
}

// exp(x) on the FMA pipe (no MUFU). ~1e-7 rel err.
__device__ __forceinline__ float fexp(float x) {
    x = fmaxf(x, -80.0f);
    float y = x * 1.4426950408889634f;
    float z = y + 12582912.0f;
    int   n = __float_as_int(z) << 23;
    float f = y - (z - 12582912.0f);
    float p = 1.5403531e-4f;
    p = fmaf(p, f, 1.3333558e-3f);
    p = fmaf(p, f, 9.6181291e-3f);
    p = fmaf(p, f, 5.5504109e-2f);
    p = fmaf(p, f, 2.4022651e-1f);
    p = fmaf(p, f, 6.9314718e-1f);
    p = fmaf(p, f, 1.0f);
    return __int_as_float(__float_as_int(p) + n);
}

// ---------------------------------------------------------------------------
// Prep: round x and all 4 weight matrices to tf32 once.
// ---------------------------------------------------------------------------
#define N4X (NTOK * HID / 4)
#define N4W (HID * HID / 4)

__global__ void __launch_bounds__(256) prep_kernel(
    const float* __restrict__ x,  const float* __restrict__ qw,
    const float* __restrict__ kw, const float* __restrict__ vw,
    const float* __restrict__ ow) {
    int i = blockIdx.x * 256 + threadIdx.x;
    const float4* s;
    float4* d;
    if (i < N4X) {
        s = (const float4*)x + i;
        d = (float4*)g_xr + i;
    } else {
        int j = i - N4X;
        int wsel = j >> 18;
        int k = j & (N4W - 1);
        const float* ws = wsel == 0 ? qw : wsel == 1 ? kw : wsel == 2 ? vw : ow;
        s = (const float4*)ws + k;
        d = (float4*)g_wr + ((size_t)wsel << 18) + k;
    }
    float4 v = *s;
    v.x = f2tff(v.x); v.y = f2tff(v.y); v.z = f2tff(v.z); v.w = f2tff(v.w);
    *d = v;
}

// ---------------------------------------------------------------------------
// TF32 GEMM core (pre-rounded): C[128x128] = A * B^T, K = 1024.
// cp.async double-buffered; sigma k-permute -> all frag loads are LDS.64.
// GP = 40 (stride ≡ 8 mod 32 banks -> conflict-free fragment loads).
// ---------------------------------------------------------------------------
#define GP 40
#define GSTRIDE (128 * GP)

__device__ __forceinline__ void gemm_core(
    const float* __restrict__ A, const float* __restrict__ B,
    int m0, int n0, float* As, float* Bs, float acc[4][4][4]) {
    const int t = threadIdx.x;
    const int w = t >> 5, lane = t & 31;
    const int wm = w >> 2, wn = w & 3;
    const int g = lane >> 2, tig = lane & 3;
    const int lr = t >> 3;           // 0..31
    const int lc = (t & 7) << 2;     // 0,4,..,28

    const float* ga = A + (size_t)(m0 + lr) * HID + lc;
    const float* gb = B + (size_t)(n0 + lr) * HID + lc;
    const uint32_t sa = smem_u32(As);
    const uint32_t sb = smem_u32(Bs);

#define GEMM_STAGE(s, buf) do {                                               \
        uint32_t off = (uint32_t)((buf) * GSTRIDE + lr * GP + lc) * 4u;       \
        _Pragma("unroll")                                                     \
        for (int p = 0; p < 4; p++) {                                         \
            CPA16(sa + off + p * (32 * GP * 4), ga + (s) * 32 + (size_t)p * 32 * HID); \
            CPA16(sb + off + p * (32 * GP * 4), gb + (s) * 32 + (size_t)p * 32 * HID); \
        }                                                                     \
    } while (0)

    GEMM_STAGE(0, 0);
    CPCOMMIT();

    for (int s = 0; s < 32; s++) {
        CPWAIT0();
        __syncthreads();
        if (s < 31) {
            GEMM_STAGE(s + 1, (s + 1) & 1);
            CPCOMMIT();
        }
        const float* Ac = As + (s & 1) * GSTRIDE;
        const float* Bc = Bs + (s & 1) * GSTRIDE;
#pragma unroll
        for (int kf = 0; kf < 4; kf++) {
            uint32_t af[4][4], bf[4][2];
#pragma unroll
            for (int mf = 0; mf < 4; mf++) {
                // sigma: frag k' = tig -> natural col 2tig; k' = tig+4 -> 2tig+1
                const float* pr = Ac + (wm * 64 + mf * 16 + g) * GP + kf * 8 + 2 * tig;
                float2 x0 = *(const float2*)pr;
                float2 x1 = *(const float2*)(pr + 8 * GP);
                af[mf][0] = __float_as_uint(x0.x);
                af[mf][1] = __float_as_uint(x1.x);
                af[mf][2] = __float_as_uint(x0.y);
                af[mf][3] = __float_as_uint(x1.y);
            }
#pragma unroll
            for (int nf = 0; nf < 4; nf++) {
                float2 b = *(const float2*)(Bc + (wn * 32 + nf * 8 + g) * GP + kf * 8 + 2 * tig);
                bf[nf][0] = __float_as_uint(b.x);
                bf[nf][1] = __float_as_uint(b.y);
            }
#pragma unroll
            for (int mf = 0; mf < 4; mf++)
#pragma unroll
                for (int nf = 0; nf < 4; nf++)
                    mma8(acc[mf][nf], af[mf][0], af[mf][1], af[mf][2], af[mf][3],
                         bf[nf][0], bf[nf][1]);
        }
    }
#undef GEMM_STAGE
}

// QKV projection. grid (32, 8, 3). Q/K head-major [B,H,S,D]; V TRANSPOSED [B,H,D,S].
__global__ void __launch_bounds__(256) qkv_gemm(
    const float* __restrict__ qb, const float* __restrict__ kb,
    const float* __restrict__ vb) {
    extern __shared__ float smf[];
    float* As = smf;
    float* Bs = smf + 2 * GSTRIDE;
    const int m0 = blockIdx.x * 128, n0 = blockIdx.y * 128;
    const float* bias; float scl;
    const float* W = g_wr + (size_t)blockIdx.z * HID * HID;
    if (blockIdx.z == 0)      { bias = qb; scl = PRIME_SCALE_F; }
    else if (blockIdx.z == 1) { bias = kb; scl = 1.0f; }
    else                      { bias = vb; scl = 1.0f; }

    float acc[4][4][4] = {};
    gemm_core(g_xr, W, m0, n0, As, Bs, acc);

    const int t = threadIdx.x, w = t >> 5, lane = t & 31;
    const int g = lane >> 2, tig = lane & 3;
    const int wm = w >> 2, wn = w & 3;
#pragma unroll
    for (int mf = 0; mf < 4; mf++) {
#pragma unroll
        for (int e = 0; e < 2; e++) {
            int m = m0 + wm * 64 + mf * 16 + g + e * 8;
            int bb = m >> 11, ss = m & 2047;
#pragma unroll
            for (int nf = 0; nf < 4; nf++) {
#pragma unroll
                for (int j = 0; j < 2; j++) {
                    int n = n0 + wn * 32 + nf * 8 + 2 * tig + j;
                    float v = f2tff((acc[mf][nf][e * 2 + j] + bias[n]) * scl);
                    int h = n >> 6, d = n & 63;
                    if (blockIdx.z == 0)
                        g_q[(((size_t)(bb * NH + h)) * SQ + ss) * HD + d] = v;
                    else if (blockIdx.z == 1)
                        g_k[(((size_t)(bb * NH + h)) * SQ + ss) * HD + d] = v;
                    else  // V transposed: [B,H,D,S]
                        g_v[(((size_t)(bb * NH + h)) * HD + d) * SQ + ss] = v;
                }
            }
        }
    }
}

// Output projection with entropy-gated scale. grid (32, 8).
__global__ void __launch_bounds__(256) out_gemm(const float* __restrict__ ob,
                                                float* __restrict__ out,
                                                float c_full) {
    extern __shared__ float smf[];
    float* As = smf;
    float* Bs = smf + 2 * GSTRIDE;
    const int m0 = blockIdx.x * 128, n0 = blockIdx.y * 128;

    float acc[4][4][4] = {};
    gemm_core(g_base, g_wr + 3 * (size_t)HID * HID, m0, n0, As, Bs, acc);

    float avg_ent = g_ent * (1.0f / 65536.0f);
    float scale = (avg_ent < 0.2f) ? 1.0f : c_full;

    const int t = threadIdx.x, w = t >> 5, lane = t & 31;
    const int g = lane >> 2, tig = lane & 3;
    const int wm = w >> 2, wn = w & 3;
#pragma unroll
    for (int mf = 0; mf < 4; mf++) {
#pragma unroll
        for (int e = 0; e < 2; e++) {
            int m = m0 + wm * 64 + mf * 16 + g + e * 8;
#pragma unroll
            for (int nf = 0; nf < 4; nf++) {
#pragma unroll
                for (int j = 0; j < 2; j++) {
                    int n = n0 + wn * 32 + nf * 8 + 2 * tig + j;
                    out[(size_t)m * HID + n] = fmaf(scale, acc[mf][nf][e * 2 + j], ob[n]);
                }
            }
        }
    }
}

// ---------------------------------------------------------------------------
// TF32 flash attention. grid (SQ/128 = 16, B*H = 32). 256 threads, 8 warps.
// sigma k-permute: B-frags are LDS.64, P stays entirely in registers (sc
// overwritten in place = PV A-operand). K smem [key][d], V smem [d][key].
// KP = 72 (stride ≡ 8 mod 32 banks -> conflict-free LDS.64).
// ---------------------------------------------------------------------------
#define KP  72
#define KVT (64 * KP)
#define ATTN_SMEM_BYTES (4 * KVT * 4 + 2 * 64 * 4 + 8 * 4)

__global__ void __launch_bounds__(256, 2) attn_tf32(const int* __restrict__ amask) {
    extern __shared__ float smf[];
    float* Kb = smf;                         // [2][64][KP]  (also Q staging early)
    float* Vb = smf + 2 * KVT;               // [2][64][KP]
    int*   mk = (int*)(smf + 4 * KVT);       // [2][64]
    float* wred = (float*)(mk + 2 * 64);     // [8]

    const int t = threadIdx.x, w = t >> 5, lane = t & 31;
    const int g = lane >> 2, tig = lane & 3;
    const int bh = blockIdx.y, q0 = blockIdx.x * 128;
    const int bb = bh >> 4, hh = bh & 15;

    const float* qp = g_q + ((size_t)bh * SQ + q0) * HD;
    const float* kp = g_k + (size_t)bh * SQ * HD;            // [key][d]
    const float* vp = g_v + (size_t)bh * HD * SQ;            // [d][key]
    const int*   mp = amask + bb * SQ;

    const uint32_t skb = smem_u32(Kb);
    const uint32_t svb = smem_u32(Vb);
    const uint32_t smk = smem_u32(mk);
    const int sr  = t >> 4;                  // 0..15
    const int sc4 = (t & 15) << 2;           // 0,4,..,60

    // ROUND-9 FIX: full-coverage staging (4x CPA16 per array per thread =
    // 64 rows x 64 cols). Previous round staged only 1/4 of each tile.
#define ATTN_STAGE(kt, buf) do {                                              \
        _Pragma("unroll")                                                     \
        for (int p = 0; p < 4; p++) {                                         \
            int rr = sr + p * 16;                                             \
            uint32_t doff = (uint32_t)((buf) * KVT + rr * KP + sc4) * 4u;     \
            CPA16(skb + doff, kp + (size_t)((kt) * 64 + rr) * HD + sc4);      \
            CPA16(svb + doff, vp + (size_t)rr * SQ + (kt) * 64 + sc4);        \
        }                                                                     \
        if (t < 16)                                                           \
            CPA16(smk + ((buf) * 64 + t * 4) * 4u, mp + (kt) * 64 + t * 4);   \
    } while (0)

    // Stage Q into Kb region (plain loads), read fragments, then release.
    {
        float* Qs = Kb;  // [128][KP]
#pragma unroll
        for (int p = 0; p < 8; p++) {
            int i = t + p * 256;
            int r = i >> 4, c4 = (i & 15) << 2;
            *(float4*)(Qs + r * KP + c4) = *(const float4*)(qp + (size_t)r * HD + c4);
        }
    }
    __syncthreads();
    uint32_t qa[8][4];
#pragma unroll
    for (int kf = 0; kf < 8; kf++) {
        // sigma: a-frag k'=tig -> natural d = 2tig; k'=tig+4 -> 2tig+1
        const float* pr = Kb + (w * 16 + g) * KP + kf * 8 + 2 * tig;
        float2 x0 = *(const float2*)pr;
        float2 x1 = *(const float2*)(pr + 8 * KP);
        qa[kf][0] = __float_as_uint(x0.x);
        qa[kf][1] = __float_as_uint(x1.x);
        qa[kf][2] = __float_as_uint(x0.y);
        qa[kf][3] = __float_as_uint(x1.y);
    }
    __syncthreads();   // everyone done reading Q before K staging overwrites

    ATTN_STAGE(0, 0);
    CPCOMMIT();

    float o[8][4] = {};
    float m0r = -1e30f, m1r = -1e30f;
    float l0 = 0.f, l1 = 0.f, t0 = 0.f, t1 = 0.f;   // per-thread partials

    for (int kt = 0; kt < 32; kt++) {
        CPWAIT0();
        __syncthreads();
        if (kt < 31) {
            ATTN_STAGE(kt + 1, (kt + 1) & 1);
            CPCOMMIT();
        }
        const float* Kt = Kb + (kt & 1) * KVT;
        const float* Vt = Vb + (kt & 1) * KVT;
        const int*   mc = mk + (kt & 1) * 64;

        // S = Q @ K^T   (B-frag: one LDS.64 per (kf,nf))
        float sc[8][4] = {};
#pragma unroll
        for (int kf = 0; kf < 8; kf++) {
#pragma unroll
            for (int nf = 0; nf < 8; nf++) {
                float2 b = *(const float2*)(Kt + (nf * 8 + g) * KP + kf * 8 + 2 * tig);
                mma8(sc[nf], qa[kf][0], qa[kf][1], qa[kf][2], qa[kf][3],
                     __float_as_uint(b.x), __float_as_uint(b.y));
            }
        }

        // mask + row max (quad reduction)
        float mx0 = -1e30f, mx1 = -1e30f;
#pragma unroll
        for (int nf = 0; nf < 8; nf++) {
            float k0 = mc[nf * 8 + 2 * tig]     ? 0.f : -1e30f;
            float k1 = mc[nf * 8 + 2 * tig + 1] ? 0.f : -1e30f;
            sc[nf][0] += k0; sc[nf][1] += k1; sc[nf][2] += k0; sc[nf][3] += k1;
            mx0 = fmaxf(mx0, fmaxf(sc[nf][0], sc[nf][1]));
            mx1 = fmaxf(mx1, fmaxf(sc[nf][2], sc[nf][3]));
        }
        mx0 = fmaxf(mx0, __shfl_xor_sync(0xffffffffu, mx0, 1));
        mx0 = fmaxf(mx0, __shfl_xor_sync(0xffffffffu, mx0, 2));
        mx1 = fmaxf(mx1, __shfl_xor_sync(0xffffffffu, mx1, 1));
        mx1 = fmaxf(mx1, __shfl_xor_sync(0xffffffffu, mx1, 2));
        float mn0 = fmaxf(m0r, mx0), mn1 = fmaxf(m1r, mx1);
        float sf0 = fexp(m0r - mn0), sf1 = fexp(m1r - mn1);
        m0r = mn0; m1r = mn1;

        // exp; accumulate per-thread partial l/t; overwrite sc with tf32(P)
        float la0 = 0.f, la1 = 0.f, ta0 = 0.f, ta1 = 0.f;
#pragma unroll
        for (int nf = 0; nf < 8; nf++) {
            float x00 = fmaxf(sc[nf][0] - mn0, -80.f);
            float x01 = fmaxf(sc[nf][1] - mn0, -80.f);
            float x10 = fmaxf(sc[nf][2] - mn1, -80.f);
            float x11 = fmaxf(sc[nf][3] - mn1, -80.f);
            float p00 = fexp(x00), p01 = fexp(x01);
            float p10 = fexp(x10), p11 = fexp(x11);
            la0 += p00 + p01; la1 += p10 + p11;
            ta0 = fmaf(p00, x00, ta0); ta0 = fmaf(p01, x01, ta0);
            ta1 = fmaf(p10, x10, ta1); ta1 = fmaf(p11, x11, ta1);
            sc[nf][0] = f2tff(p00); sc[nf][1] = f2tff(p01);
            sc[nf][2] = f2tff(p10); sc[nf][3] = f2tff(p11);
        }
        l0 = fmaf(l0, sf0, la0);
        l1 = fmaf(l1, sf1, la1);
        t0 = t0 * sf0 + ta0 + mn0 * la0;
        t1 = t1 * sf1 + ta1 + mn1 * la1;
#pragma unroll
        for (int nf = 0; nf < 8; nf++) {
            o[nf][0] *= sf0; o[nf][1] *= sf0;
            o[nf][2] *= sf1; o[nf][3] *= sf1;
        }

        // O += P @ V : A-frag straight from sc registers (sigma layout match);
        // B-frag: one LDS.64 from V^T [d][key].
#pragma unroll
        for (int kf = 0; kf < 8; kf++) {
            uint32_t a0 = __float_as_uint(sc[kf][0]);
            uint32_t a1 = __float_as_uint(sc[kf][2]);
            uint32_t a2 = __float_as_uint(sc[kf][1]);
            uint32_t a3 = __float_as_uint(sc[kf][3]);
#pragma unroll
            for (int nf = 0; nf < 8; nf++) {
                float2 b = *(const float2*)(Vt + (nf * 8 + g) * KP + kf * 8 + 2 * tig);
                mma8(o[nf], a0, a1, a2, a3,
                     __float_as_uint(b.x), __float_as_uint(b.y));
            }
        }
    }

    // Final quad reductions of l/t (deferred)
    l0 += __shfl_xor_sync(0xffffffffu, l0, 1);
    l0 += __shfl_xor_sync(0xffffffffu, l0, 2);
    l1 += __shfl_xor_sync(0xffffffffu, l1, 1);
    l1 += __shfl_xor_sync(0xffffffffu, l1, 2);
    t0 += __shfl_xor_sync(0xffffffffu, t0, 1);
    t0 += __shfl_xor_sync(0xffffffffu, t0, 2);
    t1 += __shfl_xor_sync(0xffffffffu, t1, 1);
    t1 += __shfl_xor_sync(0xffffffffu, t1, 2);

    // Write normalized O (tf32-rounded so out_gemm skips conversion)
    float inv0 = 1.0f / l0, inv1 = 1.0f / l1;
    float* ob0 = g_base + ((size_t)(bb * SQ + q0 + w * 16 + g)) * HID + hh * HD;
    float* ob1 = ob0 + 8 * HID;
#pragma unroll
    for (int nf = 0; nf < 8; nf++) {
        int c = nf * 8 + 2 * tig;
        ob0[c]     = f2tff(o[nf][0] * inv0);
        ob0[c + 1] = f2tff(o[nf][1] * inv0);
        ob1[c]     = f2tff(o[nf][2] * inv1);
        ob1[c + 1] = f2tff(o[nf][3] * inv1);
    }

    // Entropy: H_row = m + log(l) - T/l (tig==0 lanes hold unique rows)
    float h = 0.f;
    if (tig == 0)
        h = (m0r + __logf(l0) - t0 * inv0) + (m1r + __logf(l1) - t1 * inv1);
#pragma unroll
    for (int off = 16; off; off >>= 1)
        h += __shfl_xor_sync(0xffffffffu, h, off);
    if (lane == 0) wred[w] = h;
    __syncthreads();
    if (t == 0) {
        float s = 0.f;
#pragma unroll
        for (int i = 0; i < 8; i++) s += wred[i];
        atomicAdd(&g_ent, s);
    }
#undef ATTN_STAGE
}

extern "C" void kernel_launch(void* const* d_in, const int* in_sizes, int n_in,
                              void* d_out, int out_size) {
    const float* x  = (const float*)d_in[0];
    const float* qw = (const float*)d_in[1];
    const float* qb = (const float*)d_in[2];
    const float* kw = (const float*)d_in[3];
    const float* kb = (const float*)d_in[4];
    const float* vw = (const float*)d_in[5];
    const float* vb = (const float*)d_in[6];
    const float* ow = (const float*)d_in[7];
    const float* ob = (const float*)d_in[8];
    const int* amask = (const int*)d_in[9];
    float* out = (float*)d_out;

    // Collapse the deterministic blend loop: full = c * base
    double c = 1.0;
    for (int i = 1; i < 10; i++) {
        double blend = 1.0 / (1.0 + exp(-(double)i / 10.0));
        double rs = 0.5 + 0.5 * blend;
        c = (1.0 - blend) * c + blend * rs;
    }

    const int gemm_smem = 2 * 2 * GSTRIDE * 4;  // 81920 bytes
    cudaFuncSetAttribute(qkv_gemm, cudaFuncAttributeMaxDynamicSharedMemorySize, gemm_smem);
    cudaFuncSetAttribute(out_gemm, cudaFuncAttributeMaxDynamicSharedMemorySize, gemm_smem);
    cudaFuncSetAttribute(attn_tf32, cudaFuncAttributeMaxDynamicSharedMemorySize, ATTN_SMEM_BYTES);

    init_kernel<<<1, 1>>>();
    prep_kernel<<<(N4X + 4 * N4W + 255) / 256, 256>>>(x, qw, kw, vw, ow);
    qkv_gemm<<<dim3(32, 8, 3), 256, gemm_smem>>>(qb, kb, vb);
    attn_tf32<<<dim3(16, 32), 256, ATTN_SMEM_BYTES>>>(amask);
    out_gemm<<<dim3(32, 8), 256, gemm_smem>>>(ob, out, (float)c);
}

// round 11
// speedup vs baseline: 4.7442x; 1.2172x over previous
#include <cuda_runtime.h>
#include <cuda_fp16.h>
#include <math.h>
#include <stdint.h>

#define NTOK 4096
#define HID  1024
#define SQ   2048
#define NH   16
#define HD   64
#define PRIME_SCALE_F 0.047245559126404574f  /* 1/sqrt(7*64) */

// Scratch (allocation-free rule: device globals)
__device__ __half g_qh[NTOK * HID];     // fp16, [B,H,S,D] with perm16 on d
__device__ __half g_kh[NTOK * HID];     // fp16, [B,H,S,D] with perm16 on d
__device__ __half g_vh[NTOK * HID];     // fp16, [B,H,D,S] with perm16 on s
__device__ float g_base[NTOK * HID];    // tf32-rounded, [B,S,HID]
__device__ float g_xr[NTOK * HID];      // tf32-rounded input x
__device__ float g_wr[4 * HID * HID];   // tf32-rounded qw,kw,vw,ow
__device__ float g_ent;

__global__ void init_kernel() { g_ent = 0.0f; }

// ---------------------------------------------------------------------------
// helpers
// ---------------------------------------------------------------------------
__device__ __forceinline__ uint32_t f2tf(float f) {
    uint32_t r;
    asm("cvt.rna.tf32.f32 %0, %1;" : "=r"(r) : "f"(f));
    return r;
}
__device__ __forceinline__ float f2tff(float f) {
    return __uint_as_float(f2tf(f));
}

// perm16: logical in-chunk index j (0..15) -> physical position so that
// {2t,2t+1,2t+8,2t+9} become the 4 contiguous halfs at 4t..4t+3.
__device__ __forceinline__ int perm16(int i) {
    int j = i & 15;
    return (i & ~15) | (((j >> 1) & 3) * 4 + ((j >> 3) & 1) * 2 + (j & 1));
}

__device__ __forceinline__ uint32_t smem_u32(const void* p) {
    return (uint32_t)__cvta_generic_to_shared(p);
}
#define CPA16(dst_u32, src_ptr) \
    asm volatile("cp.async.ca.shared.global [%0], [%1], 16;" :: "r"(dst_u32), "l"(src_ptr))
#define CPCOMMIT() asm volatile("cp.async.commit_group;")
#define CPWAIT0()  asm volatile("cp.async.wait_group 0;")

// tf32 m16n8k8 (GEMM path)
__device__ __forceinline__ void mma8(float* c,
                                     uint32_t a0, uint32_t a1, uint32_t a2, uint32_t a3,
                                     uint32_t b0, uint32_t b1) {
    asm volatile(
        "mma.sync.aligned.m16n8k8.row.col.f32.tf32.tf32.f32 "
        "{%0,%1,%2,%3},{%4,%5,%6,%7},{%8,%9},{%0,%1,%2,%3};"
        : "+f"(c[0]), "+f"(c[1]), "+f"(c[2]), "+f"(c[3])
        : "r"(a0), "r"(a1), "r"(a2), "r"(a3), "r"(b0), "r"(b1));
}

// fp16 m16n8k16 with fp32 accumulate (attention path)
__device__ __forceinline__ void mma16(float* c,
                                      uint32_t a0, uint32_t a1, uint32_t a2, uint32_t a3,
                                      uint32_t b0, uint32_t b1) {
    asm volatile(
        "mma.sync.aligned.m16n8k16.row.col.f32.f16.f16.f32 "
        "{%0,%1,%2,%3},{%4,%5,%6,%7},{%8,%9},{%0,%1,%2,%3};"
        : "+f"(c[0]), "+f"(c[1]), "+f"(c[2]), "+f"(c[3])
        : "r"(a0), "r"(a1), "r"(a2), "r"(a3), "r"(b0), "r"(b1));
}

// pack two fp32 -> f16x2 (lo in low 16 bits). PTX cvt: first src = high half.
#define PACK_H2(r, lo, hi) \
    asm("cvt.rn.f16x2.f32 %0, %1, %2;" : "=r"(r) : "f"(hi), "f"(lo))

// exp(x) on the FMA pipe (no MUFU). ~1e-7 rel err.
__device__ __forceinline__ float fexp(float x) {
    x = fmaxf(x, -80.0f);
    float y = x * 1.4426950408889634f;
    float z = y + 12582912.0f;
    int   n = __float_as_int(z) << 23;
    float f = y - (z - 12582912.0f);
    float p = 1.5403531e-4f;
    p = fmaf(p, f, 1.3333558e-3f);
    p = fmaf(p, f, 9.6181291e-3f);
    p = fmaf(p, f, 5.5504109e-2f);
    p = fmaf(p, f, 2.4022651e-1f);
    p = fmaf(p, f, 6.9314718e-1f);
    p = fmaf(p, f, 1.0f);
    return __int_as_float(__float_as_int(p) + n);
}

// ---------------------------------------------------------------------------
// Prep: round x and all 4 weight matrices to tf32 once.
// ---------------------------------------------------------------------------
#define N4X (NTOK * HID / 4)
#define N4W (HID * HID / 4)

__global__ void __launch_bounds__(256) prep_kernel(
    const float* __restrict__ x,  const float* __restrict__ qw,
    const float* __restrict__ kw, const float* __restrict__ vw,
    const float* __restrict__ ow) {
    int i = blockIdx.x * 256 + threadIdx.x;
    const float4* s;
    float4* d;
    if (i < N4X) {
        s = (const float4*)x + i;
        d = (float4*)g_xr + i;
    } else {
        int j = i - N4X;
        int wsel = j >> 18;
        int k = j & (N4W - 1);
        const float* ws = wsel == 0 ? qw : wsel == 1 ? kw : wsel == 2 ? vw : ow;
        s = (const float4*)ws + k;
        d = (float4*)g_wr + ((size_t)wsel << 18) + k;
    }
    float4 v = *s;
    v.x = f2tff(v.x); v.y = f2tff(v.y); v.z = f2tff(v.z); v.w = f2tff(v.w);
    *d = v;
}

// ---------------------------------------------------------------------------
// TF32 GEMM core (pre-rounded): C[128x128] = A * B^T, K = 1024.
// cp.async double-buffered; sigma k-permute -> all frag loads are LDS.64.
// GP = 40 (stride ≡ 8 mod 32 banks -> conflict-free fragment loads).
// ---------------------------------------------------------------------------
#define GP 40
#define GSTRIDE (128 * GP)

__device__ __forceinline__ void gemm_core(
    const float* __restrict__ A, const float* __restrict__ B,
    int m0, int n0, float* As, float* Bs, float acc[4][4][4]) {
    const int t = threadIdx.x;
    const int w = t >> 5, lane = t & 31;
    const int wm = w >> 2, wn = w & 3;
    const int g = lane >> 2, tig = lane & 3;
    const int lr = t >> 3;           // 0..31
    const int lc = (t & 7) << 2;     // 0,4,..,28

    const float* ga = A + (size_t)(m0 + lr) * HID + lc;
    const float* gb = B + (size_t)(n0 + lr) * HID + lc;
    const uint32_t sa = smem_u32(As);
    const uint32_t sb = smem_u32(Bs);

#define GEMM_STAGE(s, buf) do {                                               \
        uint32_t off = (uint32_t)((buf) * GSTRIDE + lr * GP + lc) * 4u;       \
        _Pragma("unroll")                                                     \
        for (int p = 0; p < 4; p++) {                                         \
            CPA16(sa + off + p * (32 * GP * 4), ga + (s) * 32 + (size_t)p * 32 * HID); \
            CPA16(sb + off + p * (32 * GP * 4), gb + (s) * 32 + (size_t)p * 32 * HID); \
        }                                                                     \
    } while (0)

    GEMM_STAGE(0, 0);
    CPCOMMIT();

    for (int s = 0; s < 32; s++) {
        CPWAIT0();
        __syncthreads();
        if (s < 31) {
            GEMM_STAGE(s + 1, (s + 1) & 1);
            CPCOMMIT();
        }
        const float* Ac = As + (s & 1) * GSTRIDE;
        const float* Bc = Bs + (s & 1) * GSTRIDE;
#pragma unroll
        for (int kf = 0; kf < 4; kf++) {
            uint32_t af[4][4], bf[4][2];
#pragma unroll
            for (int mf = 0; mf < 4; mf++) {
                const float* pr = Ac + (wm * 64 + mf * 16 + g) * GP + kf * 8 + 2 * tig;
                float2 x0 = *(const float2*)pr;
                float2 x1 = *(const float2*)(pr + 8 * GP);
                af[mf][0] = __float_as_uint(x0.x);
                af[mf][1] = __float_as_uint(x1.x);
                af[mf][2] = __float_as_uint(x0.y);
                af[mf][3] = __float_as_uint(x1.y);
            }
#pragma unroll
            for (int nf = 0; nf < 4; nf++) {
                float2 b = *(const float2*)(Bc + (wn * 32 + nf * 8 + g) * GP + kf * 8 + 2 * tig);
                bf[nf][0] = __float_as_uint(b.x);
                bf[nf][1] = __float_as_uint(b.y);
            }
#pragma unroll
            for (int mf = 0; mf < 4; mf++)
#pragma unroll
                for (int nf = 0; nf < 4; nf++)
                    mma8(acc[mf][nf], af[mf][0], af[mf][1], af[mf][2], af[mf][3],
                         bf[nf][0], bf[nf][1]);
        }
    }
#undef GEMM_STAGE
}

// QKV projection. grid (32, 8, 3). Writes fp16 with perm16 layouts:
// Q/K: [B,H,S,D'] (d permuted); V: [B,H,D,S'] (s permuted).
__global__ void __launch_bounds__(256) qkv_gemm(
    const float* __restrict__ qb, const float* __restrict__ kb,
    const float* __restrict__ vb) {
    extern __shared__ float smf[];
    float* As = smf;
    float* Bs = smf + 2 * GSTRIDE;
    const int m0 = blockIdx.x * 128, n0 = blockIdx.y * 128;
    const float* bias; float scl;
    const float* W = g_wr + (size_t)blockIdx.z * HID * HID;
    if (blockIdx.z == 0)      { bias = qb; scl = PRIME_SCALE_F; }
    else if (blockIdx.z == 1) { bias = kb; scl = 1.0f; }
    else                      { bias = vb; scl = 1.0f; }

    float acc[4][4][4] = {};
    gemm_core(g_xr, W, m0, n0, As, Bs, acc);

    const int t = threadIdx.x, w = t >> 5, lane = t & 31;
    const int g = lane >> 2, tig = lane & 3;
    const int wm = w >> 2, wn = w & 3;
#pragma unroll
    for (int mf = 0; mf < 4; mf++) {
#pragma unroll
        for (int e = 0; e < 2; e++) {
            int m = m0 + wm * 64 + mf * 16 + g + e * 8;
            int bb = m >> 11, ss = m & 2047;
#pragma unroll
            for (int nf = 0; nf < 4; nf++) {
#pragma unroll
                for (int j = 0; j < 2; j++) {
                    int n = n0 + wn * 32 + nf * 8 + 2 * tig + j;
                    float v = (acc[mf][nf][e * 2 + j] + bias[n]) * scl;
                    int h = n >> 6, d = n & 63;
                    __half hv = __float2half_rn(v);
                    if (blockIdx.z == 0)
                        g_qh[(((size_t)(bb * NH + h)) * SQ + ss) * HD + perm16(d)] = hv;
                    else if (blockIdx.z == 1)
                        g_kh[(((size_t)(bb * NH + h)) * SQ + ss) * HD + perm16(d)] = hv;
                    else  // V transposed, key permuted
                        g_vh[(((size_t)(bb * NH + h)) * HD + d) * SQ + perm16(ss)] = hv;
                }
            }
        }
    }
}

// Output projection with entropy-gated scale. grid (32, 8).
__global__ void __launch_bounds__(256) out_gemm(const float* __restrict__ ob,
                                                float* __restrict__ out,
                                                float c_full) {
    extern __shared__ float smf[];
    float* As = smf;
    float* Bs = smf + 2 * GSTRIDE;
    const int m0 = blockIdx.x * 128, n0 = blockIdx.y * 128;

    float acc[4][4][4] = {};
    gemm_core(g_base, g_wr + 3 * (size_t)HID * HID, m0, n0, As, Bs, acc);

    float avg_ent = g_ent * (1.0f / 65536.0f);
    float scale = (avg_ent < 0.2f) ? 1.0f : c_full;

    const int t = threadIdx.x, w = t >> 5, lane = t & 31;
    const int g = lane >> 2, tig = lane & 3;
    const int wm = w >> 2, wn = w & 3;
#pragma unroll
    for (int mf = 0; mf < 4; mf++) {
#pragma unroll
        for (int e = 0; e < 2; e++) {
            int m = m0 + wm * 64 + mf * 16 + g + e * 8;
#pragma unroll
            for (int nf = 0; nf < 4; nf++) {
#pragma unroll
                for (int j = 0; j < 2; j++) {
                    int n = n0 + wn * 32 + nf * 8 + 2 * tig + j;
                    out[(size_t)m * HID + n] = fmaf(scale, acc[mf][nf][e * 2 + j], ob[n]);
                }
            }
        }
    }
}

// ---------------------------------------------------------------------------
// FP16 flash attention (m16n8k16, fp32 accum). grid (16, 32). 256 thr, 8 warps.
// perm16 layouts make every B-frag ONE aligned LDS.64; P stays in registers
// as packed f16x2 pairs (exact m16n8k16 A-frag layout). Q read by LDG.
// KPH = 80 halfs/row (160B ≡ 32 mod 128 -> conflict-free both phases).
// ---------------------------------------------------------------------------
#define KPH 80
#define KTILEH (64 * KPH)                       // halfs per tile (10240 B)
#define KTILEB (KTILEH * 2)
#define ATTN_SMEM_BYTES (4 * KTILEB + 2 * 64 * 4 + 8 * 4)

__global__ void __launch_bounds__(256, 2) attn_f16(const int* __restrict__ amask) {
    extern __shared__ __align__(16) char smc[];
    __half* Kb = (__half*)smc;                   // [2][KTILEH]
    __half* Vb = Kb + 2 * KTILEH;                // [2][KTILEH]
    int*    mk = (int*)(smc + 4 * KTILEB);       // [2][64]
    float*  wred = (float*)(mk + 2 * 64);        // [8]

    const int t = threadIdx.x, w = t >> 5, lane = t & 31;
    const int g = lane >> 2, tig = lane & 3;
    const int bh = blockIdx.y, q0 = blockIdx.x * 128;
    const int bb = bh >> 4, hh = bh & 15;

    const char* kpB = (const char*)(g_kh + (size_t)bh * SQ * HD);
    const char* vpB = (const char*)(g_vh + (size_t)bh * HD * SQ);
    const int*  mp  = amask + bb * SQ;

    const uint32_t skb = smem_u32(Kb);
    const uint32_t svb = smem_u32(Vb);
    const uint32_t smk = smem_u32(mk);
    const int sr2 = t >> 3;                      // 0..31
    const int sch = (t & 7) * 16;                // byte offset in 128B row

    // K rows: 64 halfs = 128B contiguous; V d-rows: slice of 128B at kt*128.
#define ATTN_STAGE(kt, buf) do {                                              \
        _Pragma("unroll")                                                     \
        for (int p = 0; p < 2; p++) {                                         \
            int row = sr2 + p * 32;                                           \
            uint32_t doff = (uint32_t)((buf) * KTILEB + row * (KPH * 2) + sch); \
            CPA16(skb + doff, kpB + (size_t)((kt) * 64 + row) * (HD * 2) + sch); \
            CPA16(svb + doff, vpB + (size_t)row * (SQ * 2) + (kt) * 128 + sch); \
        }                                                                     \
        if (t < 16)                                                           \
            CPA16(smk + ((buf) * 64 + t * 4) * 4u, mp + (kt) * 64 + t * 4);   \
    } while (0)

    // Q fragments straight from gmem (perm16 layout -> LDG.64 pairs).
    uint32_t qa[4][4];
    {
        const __half* qp = g_qh + ((size_t)bh * SQ + q0 + w * 16 + g) * HD;
#pragma unroll
        for (int kf = 0; kf < 4; kf++) {
            uint2 x0 = *(const uint2*)(qp + kf * 16 + 4 * tig);
            uint2 x1 = *(const uint2*)(qp + 8 * HD + kf * 16 + 4 * tig);
            qa[kf][0] = x0.x; qa[kf][1] = x1.x;
            qa[kf][2] = x0.y; qa[kf][3] = x1.y;
        }
    }

    ATTN_STAGE(0, 0);
    CPCOMMIT();

    float o[8][4] = {};
    float m0r = -1e30f, m1r = -1e30f;
    float l0 = 0.f, l1 = 0.f, t0 = 0.f, t1 = 0.f;   // per-thread partials

    for (int kt = 0; kt < 32; kt++) {
        CPWAIT0();
        __syncthreads();
        if (kt < 31) {
            ATTN_STAGE(kt + 1, (kt + 1) & 1);
            CPCOMMIT();
        }
        const __half* Kt = Kb + (kt & 1) * KTILEH;
        const __half* Vt = Vb + (kt & 1) * KTILEH;
        const int*    mc = mk + (kt & 1) * 64;

        // S = Q @ K^T : 4 kf x 8 nf m16n8k16 MMAs, B-frag = one LDS.64
        float sc[8][4] = {};
#pragma unroll
        for (int kf = 0; kf < 4; kf++) {
#pragma unroll
            for (int nf = 0; nf < 8; nf++) {
                uint2 b = *(const uint2*)(Kt + (nf * 8 + g) * KPH + kf * 16 + 4 * tig);
                mma16(sc[nf], qa[kf][0], qa[kf][1], qa[kf][2], qa[kf][3], b.x, b.y);
            }
        }

        // mask + row max (quad reduction)
        float mx0 = -1e30f, mx1 = -1e30f;
#pragma unroll
        for (int nf = 0; nf < 8; nf++) {
            float k0 = mc[nf * 8 + 2 * tig]     ? 0.f : -1e30f;
            float k1 = mc[nf * 8 + 2 * tig + 1] ? 0.f : -1e30f;
            sc[nf][0] += k0; sc[nf][1] += k1; sc[nf][2] += k0; sc[nf][3] += k1;
            mx0 = fmaxf(mx0, fmaxf(sc[nf][0], sc[nf][1]));
            mx1 = fmaxf(mx1, fmaxf(sc[nf][2], sc[nf][3]));
        }
        mx0 = fmaxf(mx0, __shfl_xor_sync(0xffffffffu, mx0, 1));
        mx0 = fmaxf(mx0, __shfl_xor_sync(0xffffffffu, mx0, 2));
        mx1 = fmaxf(mx1, __shfl_xor_sync(0xffffffffu, mx1, 1));
        mx1 = fmaxf(mx1, __shfl_xor_sync(0xffffffffu, mx1, 2));
        float mn0 = fmaxf(m0r, mx0), mn1 = fmaxf(m1r, mx1);
        float sf0 = fexp(m0r - mn0), sf1 = fexp(m1r - mn1);
        m0r = mn0; m1r = mn1;

        // exp in fp32; pack P to f16x2 pairs (exact PV A-frag layout)
        uint32_t pk[8][2];
        float la0 = 0.f, la1 = 0.f, ta0 = 0.f, ta1 = 0.f;
#pragma unroll
        for (int nf = 0; nf < 8; nf++) {
            float x00 = fmaxf(sc[nf][0] - mn0, -80.f);
            float x01 = fmaxf(sc[nf][1] - mn0, -80.f);
            float x10 = fmaxf(sc[nf][2] - mn1, -80.f);
            float x11 = fmaxf(sc[nf][3] - mn1, -80.f);
            float p00 = fexp(x00), p01 = fexp(x01);
            float p10 = fexp(x10), p11 = fexp(x11);
            la0 += p00 + p01; la1 += p10 + p11;
            ta0 = fmaf(p00, x00, ta0); ta0 = fmaf(p01, x01, ta0);
            ta1 = fmaf(p10, x10, ta1); ta1 = fmaf(p11, x11, ta1);
            PACK_H2(pk[nf][0], p00, p01);
            PACK_H2(pk[nf][1], p10, p11);
        }
        l0 = fmaf(l0, sf0, la0);
        l1 = fmaf(l1, sf1, la1);
        t0 = t0 * sf0 + ta0 + mn0 * la0;
        t1 = t1 * sf1 + ta1 + mn1 * la1;
#pragma unroll
        for (int nf = 0; nf < 8; nf++) {
            o[nf][0] *= sf0; o[nf][1] *= sf0;
            o[nf][2] *= sf1; o[nf][3] *= sf1;
        }

        // O += P @ V : A from pk registers; B-frag one LDS.64 from V^T.
        // kf-th k16 chunk = keys 16kf..16kf+15 = C-frags 2kf (lo 8) + 2kf+1 (hi 8)
#pragma unroll
        for (int kf = 0; kf < 4; kf++) {
            uint32_t a0 = pk[2 * kf][0];      // row g,   k 2tig,2tig+1
            uint32_t a1 = pk[2 * kf][1];      // row g+8, k 2tig,2tig+1
            uint32_t a2 = pk[2 * kf + 1][0];  // row g,   k 2tig+8,2tig+9
            uint32_t a3 = pk[2 * kf + 1][1];  // row g+8, k 2tig+8,2tig+9
#pragma unroll
            for (int nf = 0; nf < 8; nf++) {
                uint2 b = *(const uint2*)(Vt + (nf * 8 + g) * KPH + kf * 16 + 4 * tig);
                mma16(o[nf], a0, a1, a2, a3, b.x, b.y);
            }
        }
    }

    // Final quad reductions of l/t (deferred)
    l0 += __shfl_xor_sync(0xffffffffu, l0, 1);
    l0 += __shfl_xor_sync(0xffffffffu, l0, 2);
    l1 += __shfl_xor_sync(0xffffffffu, l1, 1);
    l1 += __shfl_xor_sync(0xffffffffu, l1, 2);
    t0 += __shfl_xor_sync(0xffffffffu, t0, 1);
    t0 += __shfl_xor_sync(0xffffffffu, t0, 2);
    t1 += __shfl_xor_sync(0xffffffffu, t1, 1);
    t1 += __shfl_xor_sync(0xffffffffu, t1, 2);

    // Write normalized O (tf32-rounded so out_gemm skips conversion)
    float inv0 = 1.0f / l0, inv1 = 1.0f / l1;
    float* ob0 = g_base + ((size_t)(bb * SQ + q0 + w * 16 + g)) * HID + hh * HD;
    float* ob1 = ob0 + 8 * HID;
#pragma unroll
    for (int nf = 0; nf < 8; nf++) {
        int c = nf * 8 + 2 * tig;
        ob0[c]     = f2tff(o[nf][0] * inv0);
        ob0[c + 1] = f2tff(o[nf][1] * inv0);
        ob1[c]     = f2tff(o[nf][2] * inv1);
        ob1[c + 1] = f2tff(o[nf][3] * inv1);
    }

    // Entropy: H_row = m + log(l) - T/l (tig==0 lanes hold unique rows)
    float h = 0.f;
    if (tig == 0)
        h = (m0r + __logf(l0) - t0 * inv0) + (m1r + __logf(l1) - t1 * inv1);
#pragma unroll
    for (int off = 16; off; off >>= 1)
        h += __shfl_xor_sync(0xffffffffu, h, off);
    if (lane == 0) wred[w] = h;
    __syncthreads();
    if (t == 0) {
        float s = 0.f;
#pragma unroll
        for (int i = 0; i < 8; i++) s += wred[i];
        atomicAdd(&g_ent, s);
    }
#undef ATTN_STAGE
}

extern "C" void kernel_launch(void* const* d_in, const int* in_sizes, int n_in,
                              void* d_out, int out_size) {
    const float* x  = (const float*)d_in[0];
    const float* qw = (const float*)d_in[1];
    const float* qb = (const float*)d_in[2];
    const float* kw = (const float*)d_in[3];
    const float* kb = (const float*)d_in[4];
    const float* vw = (const float*)d_in[5];
    const float* vb = (const float*)d_in[6];
    const float* ow = (const float*)d_in[7];
    const float* ob = (const float*)d_in[8];
    const int* amask = (const int*)d_in[9];
    float* out = (float*)d_out;

    // Collapse the deterministic blend loop: full = c * base
    double c = 1.0;
    for (int i = 1; i < 10; i++) {
        double blend = 1.0 / (1.0 + exp(-(double)i / 10.0));
        double rs = 0.5 + 0.5 * blend;
        c = (1.0 - blend) * c + blend * rs;
    }

    const int gemm_smem = 2 * 2 * GSTRIDE * 4;  // 81920 bytes
    cudaFuncSetAttribute(qkv_gemm, cudaFuncAttributeMaxDynamicSharedMemorySize, gemm_smem);
    cudaFuncSetAttribute(out_gemm, cudaFuncAttributeMaxDynamicSharedMemorySize, gemm_smem);
    cudaFuncSetAttribute(attn_f16, cudaFuncAttributeMaxDynamicSharedMemorySize, ATTN_SMEM_BYTES);

    init_kernel<<<1, 1>>>();
    prep_kernel<<<(N4X + 4 * N4W + 255) / 256, 256>>>(x, qw, kw, vw, ow);
    qkv_gemm<<<dim3(32, 8, 3), 256, gemm_smem>>>(qb, kb, vb);
    attn_f16<<<dim3(16, 32), 256, ATTN_SMEM_BYTES>>>(amask);
    out_gemm<<<dim3(32, 8), 256, gemm_smem>>>(ob, out, (float)c);
}